// round 10
// baseline (speedup 1.0000x reference)
#include <cuda_runtime.h>
#include <cuda_bf16.h>
#include <math.h>

// Problem constants
#define S_   2048
#define D_   1024
#define NH_  8
#define NKV_ 2
#define HD_  128
#define WS_  64
#define E_   16
#define HDIM_ 512

// ---------------- scratch (device globals; no allocation allowed) ----------------
// fp32 intermediates
__device__ float g_q[S_ * D_];
__device__ float g_k[S_ * NKV_ * HD_];
__device__ float g_v[S_ * NKV_ * HD_];
__device__ float g_x1[S_ * D_];
__device__ float g_h2[S_ * D_];
__device__ float g_contrib[S_ * 2 * D_];
__device__ float g_gate[S_ * 2];
__device__ int   g_list[E_ * S_];
__device__ int   g_cnt[E_];
__device__ float g_colsum[E_];
// bf16x2 (hi,lo) activations: [row][kpair]
__device__ unsigned g_h1h[S_ * D_ / 2],   g_h1l[S_ * D_ / 2];
__device__ unsigned g_attnh[S_ * D_ / 2], g_attnl[S_ * D_ / 2];
__device__ unsigned g_h2h[S_ * D_ / 2],   g_h2l[S_ * D_ / 2];
__device__ unsigned g_hmidh[E_ * S_ * HDIM_ / 2], g_hmidl[E_ * S_ * HDIM_ / 2];
// bf16x2 (hi,lo) weights: [kpair][n] (per expert where applicable)
__device__ unsigned g_wqh[D_ * D_ / 2],  g_wql[D_ * D_ / 2];
__device__ unsigned g_wkh[D_ * 256 / 2], g_wkl[D_ * 256 / 2];
__device__ unsigned g_wvh[D_ * 256 / 2], g_wvl[D_ * 256 / 2];
__device__ unsigned g_woh[D_ * D_ / 2],  g_wol[D_ * D_ / 2];
__device__ unsigned g_w1h[E_ * D_ * HDIM_ / 2], g_w1l[E_ * D_ * HDIM_ / 2];
__device__ unsigned g_w2h[E_ * HDIM_ * D_ / 2], g_w2l[E_ * HDIM_ * D_ / 2];

__device__ __forceinline__ void bfsplit2(float x0, float x1, unsigned& hi, unsigned& lo) {
    __nv_bfloat162 h = __float22bfloat162_rn(make_float2(x0, x1));
    float h0 = __low2float(h);
    float h1 = __high2float(h);
    __nv_bfloat162 l = __float22bfloat162_rn(make_float2(x0 - h0, x1 - h1));
    hi = *reinterpret_cast<unsigned*>(&h);
    lo = *reinterpret_cast<unsigned*>(&l);
}

// ---------------- weight prep: fp32 [K][N] -> bf16x2 hi/lo [K/2][N] ----------------
__global__ void __launch_bounds__(256) prep_kernel(const float* __restrict__ src,
                                                   unsigned* __restrict__ dh,
                                                   unsigned* __restrict__ dl, int N) {
    int n  = blockIdx.x * 256 + threadIdx.x;
    int kp = blockIdx.y;
    int K2 = gridDim.y;
    size_t so = (size_t)blockIdx.z * (size_t)(2 * K2) * N;
    size_t dofs = (size_t)blockIdx.z * (size_t)K2 * N + (size_t)kp * N + n;
    float a = src[so + (size_t)(2 * kp) * N + n];
    float b = src[so + (size_t)(2 * kp + 1) * N + n];
    unsigned h, l;
    bfsplit2(a, b, h, l);
    dh[dofs] = h;
    dl[dofs] = l;
}

// ---------------- utility kernels ----------------
__global__ void zero_kernel() {
    int t = threadIdx.x;
    if (t < E_) { g_cnt[t] = 0; g_colsum[t] = 0.f; }
}

// rmsnorm: writes bf16x2 hi/lo (and optionally fp32)
__device__ __forceinline__ void rms_row(const float* __restrict__ x,
                                        const float* __restrict__ w,
                                        unsigned* __restrict__ oh,
                                        unsigned* __restrict__ ol,
                                        float* __restrict__ ofp) {
    int n = blockIdx.x;
    int tid = threadIdx.x;
    float4 xv = *(const float4*)&x[n * D_ + tid * 4];
    float s = xv.x * xv.x + xv.y * xv.y + xv.z * xv.z + xv.w * xv.w;
    #pragma unroll
    for (int off = 16; off; off >>= 1) s += __shfl_xor_sync(0xffffffffu, s, off);
    __shared__ float part[8];
    __shared__ float inv;
    int wid = tid >> 5, lane = tid & 31;
    if (lane == 0) part[wid] = s;
    __syncthreads();
    if (tid == 0) {
        float t = 0.f;
        #pragma unroll
        for (int i = 0; i < 8; i++) t += part[i];
        inv = rsqrtf(t / (float)D_ + 1e-6f);
    }
    __syncthreads();
    float4 wv = *(const float4*)&w[tid * 4];
    float4 ov;
    ov.x = xv.x * inv * wv.x; ov.y = xv.y * inv * wv.y;
    ov.z = xv.z * inv * wv.z; ov.w = xv.w * inv * wv.w;
    uint2 hv, lv;
    bfsplit2(ov.x, ov.y, hv.x, lv.x);
    bfsplit2(ov.z, ov.w, hv.y, lv.y);
    *(uint2*)&oh[(size_t)n * (D_ / 2) + tid * 2] = hv;
    *(uint2*)&ol[(size_t)n * (D_ / 2) + tid * 2] = lv;
    if (ofp) *(float4*)&ofp[(size_t)n * D_ + tid * 4] = ov;
}

__global__ void __launch_bounds__(256) rmsnorm1_kernel(const float* __restrict__ x,
                                                       const float* __restrict__ w) {
    rms_row(x, w, g_h1h, g_h1l, nullptr);
}
__global__ void __launch_bounds__(256) rmsnorm2_kernel(const float* __restrict__ w) {
    rms_row(g_x1, w, g_h2h, g_h2l, g_h2);
}

// ================= bf16x3 tensor-core GEMM core (pre-split gmem operands) =========
// Block tile 128x128x16, 256 threads = 8 warps (2M x 4N), warp tile 64x32.
// smem: [kpair(8)][idx] bf16x2 arrays, stride 136 uints (==8 mod 32, conflict-free).
#define BK 16
#define AS 136
#define BS 136

__device__ __forceinline__ void mma16(float* d, const unsigned* a, const unsigned* b) {
    asm volatile(
        "mma.sync.aligned.m16n8k16.row.col.f32.bf16.bf16.f32 "
        "{%0,%1,%2,%3}, {%4,%5,%6,%7}, {%8,%9}, {%0,%1,%2,%3};\n"
        : "+f"(d[0]), "+f"(d[1]), "+f"(d[2]), "+f"(d[3])
        : "r"(a[0]), "r"(a[1]), "r"(a[2]), "r"(a[3]), "r"(b[0]), "r"(b[1]));
}

// aH/aL: this thread's A row base (bf16x2 [row][kp]) + akh*4
// bH/bL: B base + kp_l*ldb + (bn + col4); ldb in uints (= N)
__device__ __forceinline__ void mma_gemm2(const unsigned* __restrict__ aH,
                                          const unsigned* __restrict__ aL,
                                          const unsigned* __restrict__ bH,
                                          const unsigned* __restrict__ bL,
                                          int ldb, int T,
                                          float (&acc)[4][4][4]) {
    __shared__ __align__(16) unsigned Ah[2][8 * AS];
    __shared__ __align__(16) unsigned Al[2][8 * AS];
    __shared__ __align__(16) unsigned Bh[2][8 * BS];
    __shared__ __align__(16) unsigned Bl[2][8 * BS];
    int tid = threadIdx.x;
    int lane = tid & 31;
    int wid = tid >> 5;
    int warpM = (wid >> 2) * 64;
    int warpN = (wid & 3) * 32;
    int grp = lane >> 2, qid = lane & 3;
    int arow = tid & 127, akh = tid >> 7;      // A: row, k-half
    int kp_l = tid >> 5, col4 = (tid & 31) * 4; // B: kpair, col block

    #pragma unroll
    for (int m = 0; m < 4; m++)
        #pragma unroll
        for (int n = 0; n < 4; n++)
            #pragma unroll
            for (int r = 0; r < 4; r++) acc[m][n][r] = 0.f;

    uint4 vah, val, vbh, vbl;
    vah = *(const uint4*)(aH);
    val = *(const uint4*)(aL);
    vbh = *(const uint4*)(bH);
    vbl = *(const uint4*)(bL);
    {
        int kb = akh * 4;
        Ah[0][(kb + 0) * AS + arow] = vah.x; Ah[0][(kb + 1) * AS + arow] = vah.y;
        Ah[0][(kb + 2) * AS + arow] = vah.z; Ah[0][(kb + 3) * AS + arow] = vah.w;
        Al[0][(kb + 0) * AS + arow] = val.x; Al[0][(kb + 1) * AS + arow] = val.y;
        Al[0][(kb + 2) * AS + arow] = val.z; Al[0][(kb + 3) * AS + arow] = val.w;
        *(uint4*)&Bh[0][kp_l * BS + col4] = vbh;
        *(uint4*)&Bl[0][kp_l * BS + col4] = vbl;
    }
    __syncthreads();

    for (int t = 0; t < T; ++t) {
        int buf = t & 1;
        if (t + 1 < T) {
            vah = *(const uint4*)(aH + (t + 1) * 8);
            val = *(const uint4*)(aL + (t + 1) * 8);
            vbh = *(const uint4*)(bH + (size_t)(t + 1) * 8 * ldb);
            vbl = *(const uint4*)(bL + (size_t)(t + 1) * 8 * ldb);
        }
        const unsigned* ah = Ah[buf]; const unsigned* al = Al[buf];
        const unsigned* bh = Bh[buf]; const unsigned* bl = Bl[buf];
        unsigned afh[4][4], afl[4][4];
        #pragma unroll
        for (int mf = 0; mf < 4; mf++) {
            int rb = warpM + mf * 16 + grp;
            afh[mf][0] = ah[qid * AS + rb];
            afh[mf][1] = ah[qid * AS + rb + 8];
            afh[mf][2] = ah[(qid + 4) * AS + rb];
            afh[mf][3] = ah[(qid + 4) * AS + rb + 8];
            afl[mf][0] = al[qid * AS + rb];
            afl[mf][1] = al[qid * AS + rb + 8];
            afl[mf][2] = al[(qid + 4) * AS + rb];
            afl[mf][3] = al[(qid + 4) * AS + rb + 8];
        }
        #pragma unroll
        for (int nf = 0; nf < 4; nf++) {
            int nb = warpN + nf * 8 + grp;
            unsigned bfh[2], bfl[2];
            bfh[0] = bh[qid * BS + nb];
            bfh[1] = bh[(qid + 4) * BS + nb];
            bfl[0] = bl[qid * BS + nb];
            bfl[1] = bl[(qid + 4) * BS + nb];
            #pragma unroll
            for (int mf = 0; mf < 4; mf++) {
                mma16(acc[mf][nf], afl[mf], bfh);
                mma16(acc[mf][nf], afh[mf], bfl);
                mma16(acc[mf][nf], afh[mf], bfh);
            }
        }
        if (t + 1 < T) {
            int nb_ = buf ^ 1;
            int kb = akh * 4;
            Ah[nb_][(kb + 0) * AS + arow] = vah.x; Ah[nb_][(kb + 1) * AS + arow] = vah.y;
            Ah[nb_][(kb + 2) * AS + arow] = vah.z; Ah[nb_][(kb + 3) * AS + arow] = vah.w;
            Al[nb_][(kb + 0) * AS + arow] = val.x; Al[nb_][(kb + 1) * AS + arow] = val.y;
            Al[nb_][(kb + 2) * AS + arow] = val.z; Al[nb_][(kb + 3) * AS + arow] = val.w;
            *(uint4*)&Bh[nb_][kp_l * BS + col4] = vbh;
            *(uint4*)&Bl[nb_][kp_l * BS + col4] = vbl;
        }
        __syncthreads();
    }
}

// ---------------- fused QKV GEMM: y tiles 0-7 Q, 8-9 K, 10-11 V ----------------
__global__ void __launch_bounds__(256, 1) qkv_kernel(const float* __restrict__ bq,
                                                     const float* __restrict__ bk,
                                                     const float* __restrict__ bv) {
    int bm = blockIdx.x * 128;
    int tn = blockIdx.y;
    const unsigned *BH, *BL; const float* bias; float* C; int ldb, ldc, bn;
    if (tn < 8)       { BH = g_wqh; BL = g_wql; bias = bq; C = g_q; ldb = 1024; ldc = 1024; bn = tn * 128; }
    else if (tn < 10) { BH = g_wkh; BL = g_wkl; bias = bk; C = g_k; ldb = 256;  ldc = 256;  bn = (tn - 8) * 128; }
    else              { BH = g_wvh; BL = g_wvl; bias = bv; C = g_v; ldb = 256;  ldc = 256;  bn = (tn - 10) * 128; }
    int tid = threadIdx.x;
    int arow = tid & 127, akh = tid >> 7;
    int kp_l = tid >> 5, col4 = (tid & 31) * 4;
    float acc[4][4][4];
    mma_gemm2(g_h1h + (size_t)(bm + arow) * (D_ / 2) + akh * 4,
              g_h1l + (size_t)(bm + arow) * (D_ / 2) + akh * 4,
              BH + (size_t)kp_l * ldb + bn + col4,
              BL + (size_t)kp_l * ldb + bn + col4,
              ldb, D_ / BK, acc);
    int lane = tid & 31, wid = tid >> 5;
    int warpM = (wid >> 2) * 64, warpN = (wid & 3) * 32;
    int grp = lane >> 2, qid = lane & 3;
    #pragma unroll
    for (int mf = 0; mf < 4; mf++) {
        int r0 = bm + warpM + mf * 16 + grp;
        #pragma unroll
        for (int nf = 0; nf < 4; nf++) {
            int c0 = bn + warpN + nf * 8 + qid * 2;
            C[(size_t)r0 * ldc + c0]           = acc[mf][nf][0] + bias[c0];
            C[(size_t)r0 * ldc + c0 + 1]       = acc[mf][nf][1] + bias[c0 + 1];
            C[(size_t)(r0 + 8) * ldc + c0]     = acc[mf][nf][2] + bias[c0];
            C[(size_t)(r0 + 8) * ldc + c0 + 1] = acc[mf][nf][3] + bias[c0 + 1];
        }
    }
}

// ---------------- attention: one warp per (query, head); writes bf16 hi/lo ----------------
__global__ void __launch_bounds__(256) attn_kernel(const float* __restrict__ sinkp) {
    int i = blockIdx.x;
    int h = threadIdx.x >> 5;
    int lane = threadIdx.x & 31;
    float sink = *sinkp;
    int kh = h >> 2;
    const float4 qv = *(const float4*)&g_q[(size_t)i * D_ + h * HD_ + lane * 4];
    int jstart = i - (WS_ - 1); if (jstart < 0) jstart = 0;
    int nj = i - jstart + 1;
    const float scale = 0.08838834764831845f;
    float s0 = -1e30f, s1 = -1e30f;
    for (int jj = 0; jj < nj; ++jj) {
        int j = jstart + jj;
        float4 kv = *(const float4*)&g_k[(size_t)j * (NKV_ * HD_) + kh * HD_ + lane * 4];
        float p = qv.x * kv.x + qv.y * kv.y + qv.z * kv.z + qv.w * kv.w;
        #pragma unroll
        for (int off = 16; off; off >>= 1) p += __shfl_xor_sync(0xffffffffu, p, off);
        p *= scale;
        if (lane == (jj & 31)) { if (jj < 32) s0 = p; else s1 = p; }
    }
    float m = fmaxf(s0, s1);
    #pragma unroll
    for (int off = 16; off; off >>= 1) m = fmaxf(m, __shfl_xor_sync(0xffffffffu, m, off));
    m = fmaxf(m, sink);
    float e0 = expf(s0 - m), e1 = expf(s1 - m);
    float dsum = e0 + e1;
    #pragma unroll
    for (int off = 16; off; off >>= 1) dsum += __shfl_xor_sync(0xffffffffu, dsum, off);
    dsum += expf(sink - m);
    float4 acc = {0.f, 0.f, 0.f, 0.f};
    for (int jj = 0; jj < nj; ++jj) {
        int j = jstart + jj;
        float esel = (jj < 32) ? e0 : e1;
        float p = __shfl_sync(0xffffffffu, esel, jj & 31);
        float4 vv = *(const float4*)&g_v[(size_t)j * (NKV_ * HD_) + kh * HD_ + lane * 4];
        acc.x += p * vv.x; acc.y += p * vv.y; acc.z += p * vv.z; acc.w += p * vv.w;
    }
    float inv = 1.0f / dsum;
    acc.x *= inv; acc.y *= inv; acc.z *= inv; acc.w *= inv;
    uint2 hv, lv;
    bfsplit2(acc.x, acc.y, hv.x, lv.x);
    bfsplit2(acc.z, acc.w, hv.y, lv.y);
    size_t kp0 = (size_t)i * (D_ / 2) + h * (HD_ / 2) + lane * 2;
    *(uint2*)&g_attnh[kp0] = hv;
    *(uint2*)&g_attnl[kp0] = lv;
}

// ---------------- output projection + residual ----------------
__global__ void __launch_bounds__(256, 1) wo_kernel(const float* __restrict__ bo,
                                                    const float* __restrict__ x) {
    int bm = blockIdx.x * 128;
    int bn = blockIdx.y * 128;
    int tid = threadIdx.x;
    int arow = tid & 127, akh = tid >> 7;
    int kp_l = tid >> 5, col4 = (tid & 31) * 4;
    float acc[4][4][4];
    mma_gemm2(g_attnh + (size_t)(bm + arow) * (D_ / 2) + akh * 4,
              g_attnl + (size_t)(bm + arow) * (D_ / 2) + akh * 4,
              g_woh + (size_t)kp_l * D_ + bn + col4,
              g_wol + (size_t)kp_l * D_ + bn + col4,
              D_, D_ / BK, acc);
    int lane = tid & 31, wid = tid >> 5;
    int warpM = (wid >> 2) * 64, warpN = (wid & 3) * 32;
    int grp = lane >> 2, qid = lane & 3;
    #pragma unroll
    for (int mf = 0; mf < 4; mf++) {
        int r0 = bm + warpM + mf * 16 + grp;
        #pragma unroll
        for (int nf = 0; nf < 4; nf++) {
            int c0 = bn + warpN + nf * 8 + qid * 2;
            g_x1[(size_t)r0 * D_ + c0]           = acc[mf][nf][0] + bo[c0]     + x[(size_t)r0 * D_ + c0];
            g_x1[(size_t)r0 * D_ + c0 + 1]       = acc[mf][nf][1] + bo[c0 + 1] + x[(size_t)r0 * D_ + c0 + 1];
            g_x1[(size_t)(r0 + 8) * D_ + c0]     = acc[mf][nf][2] + bo[c0]     + x[(size_t)(r0 + 8) * D_ + c0];
            g_x1[(size_t)(r0 + 8) * D_ + c0 + 1] = acc[mf][nf][3] + bo[c0 + 1] + x[(size_t)(r0 + 8) * D_ + c0 + 1];
        }
    }
}

// ---------------- router ----------------
__global__ void __launch_bounds__(128) router_kernel(const float* __restrict__ rw,
                                                     const float* __restrict__ rb) {
    int n = blockIdx.x;
    int tid = threadIdx.x;
    float acc[16];
    #pragma unroll
    for (int e = 0; e < 16; e++) acc[e] = 0.f;
    for (int d = tid; d < D_; d += 128) {
        float hv = g_h2[(size_t)n * D_ + d];
        const float4* r4 = (const float4*)(rw + (size_t)d * E_);
        float4 r0 = r4[0], r1 = r4[1], r2 = r4[2], r3 = r4[3];
        acc[0]  += hv * r0.x; acc[1]  += hv * r0.y; acc[2]  += hv * r0.z; acc[3]  += hv * r0.w;
        acc[4]  += hv * r1.x; acc[5]  += hv * r1.y; acc[6]  += hv * r1.z; acc[7]  += hv * r1.w;
        acc[8]  += hv * r2.x; acc[9]  += hv * r2.y; acc[10] += hv * r2.z; acc[11] += hv * r2.w;
        acc[12] += hv * r3.x; acc[13] += hv * r3.y; acc[14] += hv * r3.z; acc[15] += hv * r3.w;
    }
    #pragma unroll
    for (int e = 0; e < 16; e++) {
        #pragma unroll
        for (int off = 16; off; off >>= 1) acc[e] += __shfl_xor_sync(0xffffffffu, acc[e], off);
    }
    __shared__ float part[4][16];
    __shared__ float slog[16];
    int wid = tid >> 5, lane = tid & 31;
    if (lane == 0) {
        #pragma unroll
        for (int e = 0; e < 16; e++) part[wid][e] = acc[e];
    }
    __syncthreads();
    if (tid < 16) {
        float s = part[0][tid] + part[1][tid] + part[2][tid] + part[3][tid];
        slog[tid] = (s + rb[tid]) / 0.1f;
    }
    __syncthreads();
    if (tid == 0) {
        float l[16];
        float m = -1e30f;
        #pragma unroll
        for (int e = 0; e < 16; e++) { l[e] = slog[e]; m = fmaxf(m, l[e]); }
        float sum = 0.f;
        #pragma unroll
        for (int e = 0; e < 16; e++) sum += expf(l[e] - m);
        float invs = 1.0f / sum;
        #pragma unroll
        for (int e = 0; e < 16; e++) atomicAdd(&g_colsum[e], expf(l[e] - m) * invs);
        int i1 = 0;
        #pragma unroll
        for (int e = 1; e < 16; e++) if (l[e] > l[i1]) i1 = e;
        int i2 = (i1 == 0) ? 1 : 0;
        #pragma unroll
        for (int e = 0; e < 16; e++) if (e != i1 && l[e] > l[i2]) i2 = e;
        float e2 = expf(l[i2] - l[i1]);
        g_gate[n * 2 + 0] = 1.0f / (1.0f + e2);
        g_gate[n * 2 + 1] = e2 / (1.0f + e2);
        int p0 = atomicAdd(&g_cnt[i1], 1); g_list[i1 * S_ + p0] = n * 2 + 0;
        int p1 = atomicAdd(&g_cnt[i2], 1); g_list[i2 * S_ + p1] = n * 2 + 1;
    }
}

__global__ void aux_kernel(float* __restrict__ outp) {
    float v = (threadIdx.x < 16) ? g_colsum[threadIdx.x] : 0.f;
    v = v * v;
    #pragma unroll
    for (int off = 16; off; off >>= 1) v += __shfl_xor_sync(0xffffffffu, v, off);
    if (threadIdx.x == 0) outp[0] = v * (1.0f / (float)E_) * 1e-5f;
}

// ---------------- MoE GEMM 1: hmid = silu(X_gather @ w1[e] + b1[e]) ----------------
__global__ void __launch_bounds__(256, 1) moe1_kernel(const float* __restrict__ b1) {
    int e = blockIdx.z;
    int cnt = g_cnt[e];
    int bm = blockIdx.x * 128;
    if (bm >= cnt) return;
    int bn = blockIdx.y * 128;
    int tid = threadIdx.x;
    int arow = tid & 127, akh = tid >> 7;
    int kp_l = tid >> 5, col4 = (tid & 31) * 4;
    int ar = bm + arow;
    if (ar >= cnt) ar = cnt - 1;
    int pair = g_list[e * S_ + ar];
    size_t aoff = (size_t)(pair >> 1) * (D_ / 2) + akh * 4;
    size_t boff = (size_t)e * (D_ / 2) * HDIM_ + (size_t)kp_l * HDIM_ + bn + col4;
    float acc[4][4][4];
    mma_gemm2(g_h2h + aoff, g_h2l + aoff, g_w1h + boff, g_w1l + boff,
              HDIM_, D_ / BK, acc);
    int lane = tid & 31, wid = tid >> 5;
    int warpM = (wid >> 2) * 64, warpN = (wid & 3) * 32;
    int grp = lane >> 2, qid = lane & 3;
    #pragma unroll
    for (int mf = 0; mf < 4; mf++) {
        int r0 = bm + warpM + mf * 16 + grp;
        #pragma unroll
        for (int nf = 0; nf < 4; nf++) {
            int c0 = bn + warpN + nf * 8 + qid * 2;
            #pragma unroll
            for (int rr = 0; rr < 2; rr++) {
                int r = r0 + rr * 8;
                if (r < cnt) {
                    float t0 = acc[mf][nf][rr * 2 + 0] + b1[e * HDIM_ + c0];
                    float t1 = acc[mf][nf][rr * 2 + 1] + b1[e * HDIM_ + c0 + 1];
                    float s0 = t0 / (1.0f + expf(-t0));
                    float s1 = t1 / (1.0f + expf(-t1));
                    unsigned h, l;
                    bfsplit2(s0, s1, h, l);
                    size_t o = (size_t)(e * S_ + r) * (HDIM_ / 2) + (c0 >> 1);
                    g_hmidh[o] = h;
                    g_hmidl[o] = l;
                }
            }
        }
    }
}

// ---------------- MoE GEMM 2: contrib[pair] = gate * (hmid @ w2[e] + b2[e]) ----------------
__global__ void __launch_bounds__(256, 1) moe2_kernel(const float* __restrict__ b2) {
    int e = blockIdx.z;
    int cnt = g_cnt[e];
    int bm = blockIdx.x * 128;
    if (bm >= cnt) return;
    int bn = blockIdx.y * 128;
    int tid = threadIdx.x;
    int arow = tid & 127, akh = tid >> 7;
    int kp_l = tid >> 5, col4 = (tid & 31) * 4;
    int ar = bm + arow;
    if (ar >= cnt) ar = cnt - 1;
    size_t aoff = (size_t)(e * S_ + ar) * (HDIM_ / 2) + akh * 4;
    size_t boff = (size_t)e * (HDIM_ / 2) * D_ + (size_t)kp_l * D_ + bn + col4;
    float acc[4][4][4];
    mma_gemm2(g_hmidh + aoff, g_hmidl + aoff, g_w2h + boff, g_w2l + boff,
              D_, HDIM_ / BK, acc);
    int lane = tid & 31, wid = tid >> 5;
    int warpM = (wid >> 2) * 64, warpN = (wid & 3) * 32;
    int grp = lane >> 2, qid = lane & 3;
    #pragma unroll
    for (int mf = 0; mf < 4; mf++) {
        int r0 = bm + warpM + mf * 16 + grp;
        #pragma unroll
        for (int nf = 0; nf < 4; nf++) {
            int c0 = bn + warpN + nf * 8 + qid * 2;
            #pragma unroll
            for (int rr = 0; rr < 2; rr++) {
                int r = r0 + rr * 8;
                if (r < cnt) {
                    int pair = g_list[e * S_ + r];
                    float g = g_gate[pair];
                    g_contrib[(size_t)pair * D_ + c0]     = g * (acc[mf][nf][rr * 2 + 0] + b2[e * D_ + c0]);
                    g_contrib[(size_t)pair * D_ + c0 + 1] = g * (acc[mf][nf][rr * 2 + 1] + b2[e * D_ + c0 + 1]);
                }
            }
        }
    }
}

// ---------------- final combine ----------------
__global__ void __launch_bounds__(256) combine_kernel(float* __restrict__ out) {
    int n = blockIdx.x;
    int d = threadIdx.x * 4;
    float4 a = *(const float4*)&g_x1[(size_t)n * D_ + d];
    float4 b = *(const float4*)&g_contrib[(size_t)(n * 2 + 0) * D_ + d];
    float4 c = *(const float4*)&g_contrib[(size_t)(n * 2 + 1) * D_ + d];
    float4 r;
    r.x = a.x + b.x + c.x; r.y = a.y + b.y + c.y;
    r.z = a.z + b.z + c.z; r.w = a.w + b.w + c.w;
    *(float4*)&out[(size_t)n * D_ + d] = r;
}

// ---------------- host launcher ----------------
extern "C" void kernel_launch(void* const* d_in, const int* in_sizes, int n_in,
                              void* d_out, int out_size) {
    const float* x    = (const float*)d_in[0];
    const float* n1w  = (const float*)d_in[1];
    const float* wq   = (const float*)d_in[2];
    const float* bq   = (const float*)d_in[3];
    const float* wk   = (const float*)d_in[4];
    const float* bk   = (const float*)d_in[5];
    const float* wv   = (const float*)d_in[6];
    const float* bv   = (const float*)d_in[7];
    const float* woW  = (const float*)d_in[8];
    const float* bo   = (const float*)d_in[9];
    const float* sink = (const float*)d_in[10];
    const float* n2w  = (const float*)d_in[11];
    const float* rw   = (const float*)d_in[12];
    const float* rb   = (const float*)d_in[13];
    const float* w1   = (const float*)d_in[14];
    const float* b1   = (const float*)d_in[15];
    const float* w2   = (const float*)d_in[16];
    const float* b2   = (const float*)d_in[17];
    float* out = (float*)d_out;

    unsigned *wqh, *wql, *wkh, *wkl, *wvh, *wvl, *woh, *wol, *w1h, *w1l, *w2h, *w2l;
    cudaGetSymbolAddress((void**)&wqh, g_wqh); cudaGetSymbolAddress((void**)&wql, g_wql);
    cudaGetSymbolAddress((void**)&wkh, g_wkh); cudaGetSymbolAddress((void**)&wkl, g_wkl);
    cudaGetSymbolAddress((void**)&wvh, g_wvh); cudaGetSymbolAddress((void**)&wvl, g_wvl);
    cudaGetSymbolAddress((void**)&woh, g_woh); cudaGetSymbolAddress((void**)&wol, g_wol);
    cudaGetSymbolAddress((void**)&w1h, g_w1h); cudaGetSymbolAddress((void**)&w1l, g_w1l);
    cudaGetSymbolAddress((void**)&w2h, g_w2h); cudaGetSymbolAddress((void**)&w2l, g_w2l);

    zero_kernel<<<1, 32>>>();
    // weight pre-split (fp32 -> bf16x2 hi/lo, [K/2][N] layout)
    prep_kernel<<<dim3(4, 512, 1),  256>>>(wq,  wqh, wql, 1024);
    prep_kernel<<<dim3(1, 512, 1),  256>>>(wk,  wkh, wkl, 256);
    prep_kernel<<<dim3(1, 512, 1),  256>>>(wv,  wvh, wvl, 256);
    prep_kernel<<<dim3(4, 512, 1),  256>>>(woW, woh, wol, 1024);
    prep_kernel<<<dim3(2, 512, 16), 256>>>(w1,  w1h, w1l, 512);
    prep_kernel<<<dim3(4, 256, 16), 256>>>(w2,  w2h, w2l, 1024);

    rmsnorm1_kernel<<<S_, 256>>>(x, n1w);
    qkv_kernel<<<dim3(S_ / 128, 12), 256>>>(bq, bk, bv);
    attn_kernel<<<S_, 256>>>(sink);
    wo_kernel<<<dim3(S_ / 128, D_ / 128), 256>>>(bo, x);
    rmsnorm2_kernel<<<S_, 256>>>(n2w);
    router_kernel<<<S_, 128>>>(rw, rb);
    if (out_size > S_ * D_) {
        aux_kernel<<<1, 32>>>(out + (size_t)S_ * D_);
    }
    moe1_kernel<<<dim3(S_ / 128, HDIM_ / 128, E_), 256>>>(b1);
    moe2_kernel<<<dim3(S_ / 128, D_ / 128, E_), 256>>>(b2);
    combine_kernel<<<S_, 256>>>(out);
}

// round 13
// speedup vs baseline: 1.1358x; 1.1358x over previous
#include <cuda_runtime.h>
#include <cuda_bf16.h>
#include <cuda_fp16.h>
#include <cstdint>
#include <math.h>

// Problem constants
#define S_   2048
#define D_   1024
#define NH_  8
#define NKV_ 2
#define HD_  128
#define WS_  64
#define E_   16
#define HDIM_ 512

// ---------------- scratch (device globals; no allocation allowed) ----------------
__device__ float g_h1[S_ * D_];
__device__ float g_q[S_ * D_];
__device__ float g_k[S_ * NKV_ * HD_];
__device__ float g_v[S_ * NKV_ * HD_];
__device__ float g_attn[S_ * D_];
__device__ float g_x1[S_ * D_];
__device__ float g_h2[S_ * D_];
__device__ float g_hmid[E_ * S_ * HDIM_];
__device__ float g_contrib[S_ * 2 * D_];
__device__ float g_gate[S_ * 2];
__device__ int   g_list[E_ * S_];
__device__ int   g_cnt[E_];
__device__ float g_colsum[E_];

// ---------------- utility kernels ----------------
__global__ void zero_kernel() {
    int t = threadIdx.x;
    if (t < E_) { g_cnt[t] = 0; g_colsum[t] = 0.f; }
}

__device__ __forceinline__ void rms_row(const float* __restrict__ x,
                                        const float* __restrict__ w,
                                        float* __restrict__ o) {
    int n = blockIdx.x;
    int tid = threadIdx.x;
    float4 xv = *(const float4*)&x[n * D_ + tid * 4];
    float s = xv.x * xv.x + xv.y * xv.y + xv.z * xv.z + xv.w * xv.w;
    #pragma unroll
    for (int off = 16; off; off >>= 1) s += __shfl_xor_sync(0xffffffffu, s, off);
    __shared__ float part[8];
    __shared__ float inv;
    int wid = tid >> 5, lane = tid & 31;
    if (lane == 0) part[wid] = s;
    __syncthreads();
    if (tid == 0) {
        float t = 0.f;
        #pragma unroll
        for (int i = 0; i < 8; i++) t += part[i];
        inv = rsqrtf(t / (float)D_ + 1e-6f);
    }
    __syncthreads();
    float4 wv = *(const float4*)&w[tid * 4];
    float4 ov;
    ov.x = xv.x * inv * wv.x; ov.y = xv.y * inv * wv.y;
    ov.z = xv.z * inv * wv.z; ov.w = xv.w * inv * wv.w;
    *(float4*)&o[n * D_ + tid * 4] = ov;
}

__global__ void __launch_bounds__(256) rmsnorm1_kernel(const float* __restrict__ x,
                                                       const float* __restrict__ w) {
    rms_row(x, w, g_h1);
}
__global__ void __launch_bounds__(256) rmsnorm2_kernel(const float* __restrict__ w) {
    rms_row(g_x1, w, g_h2);
}

// ================= fp16x2 tensor-core GEMM core =================
// Block tile 128x64x16, 128 threads = 4 warps (2x2), warp tile 64x32.
// A split into (hi,lo) fp16 at staging; B rounded once to fp16.
// smem holds fp16x2 k-pairs:
//   A: [kpair(8)][row(128)] stride 136 (==8 mod 32 -> conflict-free frag LDS)
//   B: [kpair(8)][col(64)]  stride 72
// 2 mma.m16n8k16 per (mf,nf) per K-tile: al*bh + ah*bh = a*bh.
// Dropped term a*bl ~ 2^-12 relative -> rel_err ~4e-4 (passes 1e-3).
#define BM 128
#define BN 64
#define BK 16
#define KP 8
#define AS 136
#define BS 72

__device__ __forceinline__ void hsplit2(float x0, float x1, unsigned& hi, unsigned& lo) {
    __half2 h = __float22half2_rn(make_float2(x0, x1));
    float h0 = __low2float(h);
    float h1 = __high2float(h);
    __half2 l = __float22half2_rn(make_float2(x0 - h0, x1 - h1));
    hi = *reinterpret_cast<unsigned*>(&h);
    lo = *reinterpret_cast<unsigned*>(&l);
}
__device__ __forceinline__ unsigned hpack2(float x0, float x1) {
    __half2 h = __float22half2_rn(make_float2(x0, x1));
    return *reinterpret_cast<unsigned*>(&h);
}

__device__ __forceinline__ void mma16(float* d, const unsigned* a, const unsigned* b) {
    asm volatile(
        "mma.sync.aligned.m16n8k16.row.col.f32.f16.f16.f32 "
        "{%0,%1,%2,%3}, {%4,%5,%6,%7}, {%8,%9}, {%0,%1,%2,%3};\n"
        : "+f"(d[0]), "+f"(d[1]), "+f"(d[2]), "+f"(d[3])
        : "r"(a[0]), "r"(a[1]), "r"(a[2]), "r"(a[3]), "r"(b[0]), "r"(b[1]));
}

// aRow: this thread's A row base (row bm+tid), contiguous K.
// bPtr: B + bn (row-major, leading dim ldb over K rows).
__device__ __forceinline__ void mma_gemm(const float* __restrict__ aRow,
                                         const float* __restrict__ bPtr,
                                         int ldb, int Kdim,
                                         float (&acc)[4][4][4]) {
    __shared__ __align__(16) unsigned Ah[2][KP * AS];
    __shared__ __align__(16) unsigned Al[2][KP * AS];
    __shared__ __align__(16) unsigned Bh[2][KP * BS];
    int tid = threadIdx.x;
    int lane = tid & 31;
    int wid = tid >> 5;
    int warpM = (wid >> 1) * 64;
    int warpN = (wid & 1) * 32;
    int grp = lane >> 2, qid = lane & 3;
    int nc = (tid & 15) * 4;            // B staging col
    int kp = tid >> 4;                  // B staging kpair 0..7

    #pragma unroll
    for (int m = 0; m < 4; m++)
        #pragma unroll
        for (int n = 0; n < 4; n++)
            #pragma unroll
            for (int r = 0; r < 4; r++) acc[m][n][r] = 0.f;

    float4 ar[4]; float4 br[2];
    // prologue: load K-tile 0, split+stage into buffer 0
    #pragma unroll
    for (int i = 0; i < 4; i++) ar[i] = *(const float4*)(aRow + i * 4);
    br[0] = *(const float4*)(bPtr + (size_t)(2 * kp) * ldb + nc);
    br[1] = *(const float4*)(bPtr + (size_t)(2 * kp + 1) * ldb + nc);
    {
        #pragma unroll
        for (int i = 0; i < 4; i++) {
            unsigned h, l;
            hsplit2(ar[i].x, ar[i].y, h, l);
            Ah[0][(2 * i) * AS + tid] = h; Al[0][(2 * i) * AS + tid] = l;
            hsplit2(ar[i].z, ar[i].w, h, l);
            Ah[0][(2 * i + 1) * AS + tid] = h; Al[0][(2 * i + 1) * AS + tid] = l;
        }
        uint4 hv;
        hv.x = hpack2(br[0].x, br[1].x);
        hv.y = hpack2(br[0].y, br[1].y);
        hv.z = hpack2(br[0].z, br[1].z);
        hv.w = hpack2(br[0].w, br[1].w);
        *(uint4*)&Bh[0][kp * BS + nc] = hv;
    }
    __syncthreads();

    int T = Kdim / BK;
    for (int t = 0; t < T; ++t) {
        int buf = t & 1;
        if (t + 1 < T) {   // prefetch next K-tile into registers
            int k0 = (t + 1) * BK;
            #pragma unroll
            for (int i = 0; i < 4; i++) ar[i] = *(const float4*)(aRow + k0 + i * 4);
            br[0] = *(const float4*)(bPtr + (size_t)(k0 + 2 * kp) * ldb + nc);
            br[1] = *(const float4*)(bPtr + (size_t)(k0 + 2 * kp + 1) * ldb + nc);
        }
        const unsigned* ah = Ah[buf]; const unsigned* al = Al[buf];
        const unsigned* bh = Bh[buf];
        // A fragments for all 4 mf
        unsigned afh[4][4], afl[4][4];
        #pragma unroll
        for (int mf = 0; mf < 4; mf++) {
            int rb = warpM + mf * 16 + grp;
            afh[mf][0] = ah[qid * AS + rb];
            afh[mf][1] = ah[qid * AS + rb + 8];
            afh[mf][2] = ah[(qid + 4) * AS + rb];
            afh[mf][3] = ah[(qid + 4) * AS + rb + 8];
            afl[mf][0] = al[qid * AS + rb];
            afl[mf][1] = al[qid * AS + rb + 8];
            afl[mf][2] = al[(qid + 4) * AS + rb];
            afl[mf][3] = al[(qid + 4) * AS + rb + 8];
        }
        #pragma unroll
        for (int nf = 0; nf < 4; nf++) {
            int nb = warpN + nf * 8 + grp;
            unsigned bfh[2];
            bfh[0] = bh[qid * BS + nb];
            bfh[1] = bh[(qid + 4) * BS + nb];
            #pragma unroll
            for (int mf = 0; mf < 4; mf++) {
                mma16(acc[mf][nf], afl[mf], bfh);
                mma16(acc[mf][nf], afh[mf], bfh);
            }
        }
        if (t + 1 < T) {   // stage prefetched tile into other buffer
            int nb_ = buf ^ 1;
            #pragma unroll
            for (int i = 0; i < 4; i++) {
                unsigned h, l;
                hsplit2(ar[i].x, ar[i].y, h, l);
                Ah[nb_][(2 * i) * AS + tid] = h; Al[nb_][(2 * i) * AS + tid] = l;
                hsplit2(ar[i].z, ar[i].w, h, l);
                Ah[nb_][(2 * i + 1) * AS + tid] = h; Al[nb_][(2 * i + 1) * AS + tid] = l;
            }
            uint4 hv;
            hv.x = hpack2(br[0].x, br[1].x);
            hv.y = hpack2(br[0].y, br[1].y);
            hv.z = hpack2(br[0].z, br[1].z);
            hv.w = hpack2(br[0].w, br[1].w);
            *(uint4*)&Bh[nb_][kp * BS + nc] = hv;
        }
        __syncthreads();
    }
}

// ---------------- fused QKV GEMM: y tiles 0-15 Q, 16-19 K, 20-23 V ----------------
__global__ void __launch_bounds__(128) qkv_kernel(const float* __restrict__ wq, const float* __restrict__ bq,
                                                  const float* __restrict__ wk, const float* __restrict__ bk,
                                                  const float* __restrict__ wv, const float* __restrict__ bv) {
    int bm = blockIdx.x * BM;
    int tn = blockIdx.y;
    const float *B, *bias; float* C; int ldb, ldc, bn;
    if (tn < 16)      { B = wq; bias = bq; C = g_q; ldb = 1024; ldc = 1024; bn = tn * 64; }
    else if (tn < 20) { B = wk; bias = bk; C = g_k; ldb = 256;  ldc = 256;  bn = (tn - 16) * 64; }
    else              { B = wv; bias = bv; C = g_v; ldb = 256;  ldc = 256;  bn = (tn - 20) * 64; }
    float acc[4][4][4];
    const float* aRow = g_h1 + (size_t)(bm + threadIdx.x) * D_;
    mma_gemm(aRow, B + bn, ldb, D_, acc);
    int lane = threadIdx.x & 31, wid = threadIdx.x >> 5;
    int warpM = (wid >> 1) * 64, warpN = (wid & 1) * 32;
    int grp = lane >> 2, qid = lane & 3;
    #pragma unroll
    for (int mf = 0; mf < 4; mf++) {
        int r0 = bm + warpM + mf * 16 + grp;
        #pragma unroll
        for (int nf = 0; nf < 4; nf++) {
            int c0 = bn + warpN + nf * 8 + qid * 2;
            C[(size_t)r0 * ldc + c0]           = acc[mf][nf][0] + bias[c0];
            C[(size_t)r0 * ldc + c0 + 1]       = acc[mf][nf][1] + bias[c0 + 1];
            C[(size_t)(r0 + 8) * ldc + c0]     = acc[mf][nf][2] + bias[c0];
            C[(size_t)(r0 + 8) * ldc + c0 + 1] = acc[mf][nf][3] + bias[c0 + 1];
        }
    }
}

// ---------------- attention: one warp per (query, head) ----------------
__global__ void __launch_bounds__(256) attn_kernel(const float* __restrict__ sinkp) {
    int i = blockIdx.x;
    int h = threadIdx.x >> 5;
    int lane = threadIdx.x & 31;
    float sink = *sinkp;
    int kh = h >> 2;
    const float4 qv = *(const float4*)&g_q[(size_t)i * D_ + h * HD_ + lane * 4];
    int jstart = i - (WS_ - 1); if (jstart < 0) jstart = 0;
    int nj = i - jstart + 1;
    const float scale = 0.08838834764831845f;
    float s0 = -1e30f, s1 = -1e30f;
    for (int jj = 0; jj < nj; ++jj) {
        int j = jstart + jj;
        float4 kv = *(const float4*)&g_k[(size_t)j * (NKV_ * HD_) + kh * HD_ + lane * 4];
        float p = qv.x * kv.x + qv.y * kv.y + qv.z * kv.z + qv.w * kv.w;
        #pragma unroll
        for (int off = 16; off; off >>= 1) p += __shfl_xor_sync(0xffffffffu, p, off);
        p *= scale;
        if (lane == (jj & 31)) { if (jj < 32) s0 = p; else s1 = p; }
    }
    float m = fmaxf(s0, s1);
    #pragma unroll
    for (int off = 16; off; off >>= 1) m = fmaxf(m, __shfl_xor_sync(0xffffffffu, m, off));
    m = fmaxf(m, sink);
    float e0 = expf(s0 - m), e1 = expf(s1 - m);
    float dsum = e0 + e1;
    #pragma unroll
    for (int off = 16; off; off >>= 1) dsum += __shfl_xor_sync(0xffffffffu, dsum, off);
    dsum += expf(sink - m);
    float4 acc = {0.f, 0.f, 0.f, 0.f};
    for (int jj = 0; jj < nj; ++jj) {
        int j = jstart + jj;
        float esel = (jj < 32) ? e0 : e1;
        float p = __shfl_sync(0xffffffffu, esel, jj & 31);
        float4 vv = *(const float4*)&g_v[(size_t)j * (NKV_ * HD_) + kh * HD_ + lane * 4];
        acc.x += p * vv.x; acc.y += p * vv.y; acc.z += p * vv.z; acc.w += p * vv.w;
    }
    float inv = 1.0f / dsum;
    acc.x *= inv; acc.y *= inv; acc.z *= inv; acc.w *= inv;
    *(float4*)&g_attn[(size_t)i * D_ + h * HD_ + lane * 4] = acc;
}

// ---------------- output projection + residual ----------------
__global__ void __launch_bounds__(128) wo_kernel(const float* __restrict__ woW, const float* __restrict__ bo,
                                                 const float* __restrict__ x) {
    int bm = blockIdx.x * BM;
    int bn = blockIdx.y * BN;
    float acc[4][4][4];
    const float* aRow = g_attn + (size_t)(bm + threadIdx.x) * D_;
    mma_gemm(aRow, woW + bn, D_, D_, acc);
    int lane = threadIdx.x & 31, wid = threadIdx.x >> 5;
    int warpM = (wid >> 1) * 64, warpN = (wid & 1) * 32;
    int grp = lane >> 2, qid = lane & 3;
    #pragma unroll
    for (int mf = 0; mf < 4; mf++) {
        int r0 = bm + warpM + mf * 16 + grp;
        #pragma unroll
        for (int nf = 0; nf < 4; nf++) {
            int c0 = bn + warpN + nf * 8 + qid * 2;
            g_x1[(size_t)r0 * D_ + c0]           = acc[mf][nf][0] + bo[c0]     + x[(size_t)r0 * D_ + c0];
            g_x1[(size_t)r0 * D_ + c0 + 1]       = acc[mf][nf][1] + bo[c0 + 1] + x[(size_t)r0 * D_ + c0 + 1];
            g_x1[(size_t)(r0 + 8) * D_ + c0]     = acc[mf][nf][2] + bo[c0]     + x[(size_t)(r0 + 8) * D_ + c0];
            g_x1[(size_t)(r0 + 8) * D_ + c0 + 1] = acc[mf][nf][3] + bo[c0 + 1] + x[(size_t)(r0 + 8) * D_ + c0 + 1];
        }
    }
}

// ---------------- router ----------------
__global__ void __launch_bounds__(128) router_kernel(const float* __restrict__ rw,
                                                     const float* __restrict__ rb) {
    int n = blockIdx.x;
    int tid = threadIdx.x;
    float acc[16];
    #pragma unroll
    for (int e = 0; e < 16; e++) acc[e] = 0.f;
    for (int d = tid; d < D_; d += 128) {
        float hv = g_h2[(size_t)n * D_ + d];
        const float4* r4 = (const float4*)(rw + (size_t)d * E_);
        float4 r0 = r4[0], r1 = r4[1], r2 = r4[2], r3 = r4[3];
        acc[0]  += hv * r0.x; acc[1]  += hv * r0.y; acc[2]  += hv * r0.z; acc[3]  += hv * r0.w;
        acc[4]  += hv * r1.x; acc[5]  += hv * r1.y; acc[6]  += hv * r1.z; acc[7]  += hv * r1.w;
        acc[8]  += hv * r2.x; acc[9]  += hv * r2.y; acc[10] += hv * r2.z; acc[11] += hv * r2.w;
        acc[12] += hv * r3.x; acc[13] += hv * r3.y; acc[14] += hv * r3.z; acc[15] += hv * r3.w;
    }
    #pragma unroll
    for (int e = 0; e < 16; e++) {
        #pragma unroll
        for (int off = 16; off; off >>= 1) acc[e] += __shfl_xor_sync(0xffffffffu, acc[e], off);
    }
    __shared__ float part[4][16];
    __shared__ float slog[16];
    int wid = tid >> 5, lane = tid & 31;
    if (lane == 0) {
        #pragma unroll
        for (int e = 0; e < 16; e++) part[wid][e] = acc[e];
    }
    __syncthreads();
    if (tid < 16) {
        float s = part[0][tid] + part[1][tid] + part[2][tid] + part[3][tid];
        slog[tid] = (s + rb[tid]) / 0.1f;
    }
    __syncthreads();
    if (tid == 0) {
        float l[16];
        float m = -1e30f;
        #pragma unroll
        for (int e = 0; e < 16; e++) { l[e] = slog[e]; m = fmaxf(m, l[e]); }
        float sum = 0.f;
        #pragma unroll
        for (int e = 0; e < 16; e++) sum += expf(l[e] - m);
        float invs = 1.0f / sum;
        #pragma unroll
        for (int e = 0; e < 16; e++) atomicAdd(&g_colsum[e], expf(l[e] - m) * invs);
        int i1 = 0;
        #pragma unroll
        for (int e = 1; e < 16; e++) if (l[e] > l[i1]) i1 = e;
        int i2 = (i1 == 0) ? 1 : 0;
        #pragma unroll
        for (int e = 0; e < 16; e++) if (e != i1 && l[e] > l[i2]) i2 = e;
        float e2 = expf(l[i2] - l[i1]);
        g_gate[n * 2 + 0] = 1.0f / (1.0f + e2);
        g_gate[n * 2 + 1] = e2 / (1.0f + e2);
        int p0 = atomicAdd(&g_cnt[i1], 1); g_list[i1 * S_ + p0] = n * 2 + 0;
        int p1 = atomicAdd(&g_cnt[i2], 1); g_list[i2 * S_ + p1] = n * 2 + 1;
    }
}

__global__ void aux_kernel(float* __restrict__ outp) {
    float v = (threadIdx.x < 16) ? g_colsum[threadIdx.x] : 0.f;
    v = v * v;
    #pragma unroll
    for (int off = 16; off; off >>= 1) v += __shfl_xor_sync(0xffffffffu, v, off);
    if (threadIdx.x == 0) outp[0] = v * (1.0f / (float)E_) * 1e-5f;
}

// ---------------- MoE GEMM 1: hmid = silu(X_gather @ w1[e] + b1[e]) ----------------
__global__ void __launch_bounds__(128) moe1_kernel(const float* __restrict__ w1,
                                                   const float* __restrict__ b1) {
    int e = blockIdx.z;
    int cnt = g_cnt[e];
    int bm = blockIdx.x * BM;
    if (bm >= cnt) return;
    int bn = blockIdx.y * BN;
    int ar = bm + threadIdx.x;
    if (ar >= cnt) ar = cnt - 1;
    int pair = g_list[e * S_ + ar];
    const float* aRow = g_h2 + (size_t)(pair >> 1) * D_;
    float acc[4][4][4];
    mma_gemm(aRow, w1 + (size_t)e * D_ * HDIM_ + bn, HDIM_, D_, acc);
    int lane = threadIdx.x & 31, wid = threadIdx.x >> 5;
    int warpM = (wid >> 1) * 64, warpN = (wid & 1) * 32;
    int grp = lane >> 2, qid = lane & 3;
    #pragma unroll
    for (int mf = 0; mf < 4; mf++) {
        int r0 = bm + warpM + mf * 16 + grp;
        #pragma unroll
        for (int nf = 0; nf < 4; nf++) {
            int c0 = bn + warpN + nf * 8 + qid * 2;
            #pragma unroll
            for (int rr = 0; rr < 2; rr++) {
                int r = r0 + rr * 8;
                if (r < cnt) {
                    float t0 = acc[mf][nf][rr * 2 + 0] + b1[e * HDIM_ + c0];
                    float t1 = acc[mf][nf][rr * 2 + 1] + b1[e * HDIM_ + c0 + 1];
                    g_hmid[(size_t)(e * S_ + r) * HDIM_ + c0]     = t0 / (1.0f + expf(-t0));
                    g_hmid[(size_t)(e * S_ + r) * HDIM_ + c0 + 1] = t1 / (1.0f + expf(-t1));
                }
            }
        }
    }
}

// ---------------- MoE GEMM 2: contrib[pair] = gate * (hmid @ w2[e] + b2[e]) ----------------
__global__ void __launch_bounds__(128) moe2_kernel(const float* __restrict__ w2,
                                                   const float* __restrict__ b2) {
    int e = blockIdx.z;
    int cnt = g_cnt[e];
    int bm = blockIdx.x * BM;
    if (bm >= cnt) return;
    int bn = blockIdx.y * BN;
    int ar = bm + threadIdx.x;
    if (ar >= cnt) ar = cnt - 1;
    const float* aRow = g_hmid + (size_t)(e * S_ + ar) * HDIM_;
    float acc[4][4][4];
    mma_gemm(aRow, w2 + (size_t)e * HDIM_ * D_ + bn, D_, HDIM_, acc);
    int lane = threadIdx.x & 31, wid = threadIdx.x >> 5;
    int warpM = (wid >> 1) * 64, warpN = (wid & 1) * 32;
    int grp = lane >> 2, qid = lane & 3;
    #pragma unroll
    for (int mf = 0; mf < 4; mf++) {
        int r0 = bm + warpM + mf * 16 + grp;
        #pragma unroll
        for (int nf = 0; nf < 4; nf++) {
            int c0 = bn + warpN + nf * 8 + qid * 2;
            #pragma unroll
            for (int rr = 0; rr < 2; rr++) {
                int r = r0 + rr * 8;
                if (r < cnt) {
                    int pair = g_list[e * S_ + r];
                    float g = g_gate[pair];
                    g_contrib[(size_t)pair * D_ + c0]     = g * (acc[mf][nf][rr * 2 + 0] + b2[e * D_ + c0]);
                    g_contrib[(size_t)pair * D_ + c0 + 1] = g * (acc[mf][nf][rr * 2 + 1] + b2[e * D_ + c0 + 1]);
                }
            }
        }
    }
}

// ---------------- final combine ----------------
__global__ void __launch_bounds__(256) combine_kernel(float* __restrict__ out) {
    int n = blockIdx.x;
    int d = threadIdx.x * 4;
    float4 a = *(const float4*)&g_x1[(size_t)n * D_ + d];
    float4 b = *(const float4*)&g_contrib[(size_t)(n * 2 + 0) * D_ + d];
    float4 c = *(const float4*)&g_contrib[(size_t)(n * 2 + 1) * D_ + d];
    float4 r;
    r.x = a.x + b.x + c.x; r.y = a.y + b.y + c.y;
    r.z = a.z + b.z + c.z; r.w = a.w + b.w + c.w;
    *(float4*)&out[(size_t)n * D_ + d] = r;
}

// ---------------- host launcher ----------------
extern "C" void kernel_launch(void* const* d_in, const int* in_sizes, int n_in,
                              void* d_out, int out_size) {
    const float* x    = (const float*)d_in[0];
    const float* n1w  = (const float*)d_in[1];
    const float* wq   = (const float*)d_in[2];
    const float* bq   = (const float*)d_in[3];
    const float* wk   = (const float*)d_in[4];
    const float* bk   = (const float*)d_in[5];
    const float* wv   = (const float*)d_in[6];
    const float* bv   = (const float*)d_in[7];
    const float* woW  = (const float*)d_in[8];
    const float* bo   = (const float*)d_in[9];
    const float* sink = (const float*)d_in[10];
    const float* n2w  = (const float*)d_in[11];
    const float* rw   = (const float*)d_in[12];
    const float* rb   = (const float*)d_in[13];
    const float* w1   = (const float*)d_in[14];
    const float* b1   = (const float*)d_in[15];
    const float* w2   = (const float*)d_in[16];
    const float* b2   = (const float*)d_in[17];
    float* out = (float*)d_out;

    zero_kernel<<<1, 32>>>();
    rmsnorm1_kernel<<<S_, 256>>>(x, n1w);
    qkv_kernel<<<dim3(S_ / BM, 24), 128>>>(wq, bq, wk, bk, wv, bv);
    attn_kernel<<<S_, 256>>>(sink);
    wo_kernel<<<dim3(S_ / BM, D_ / BN), 128>>>(woW, bo, x);
    rmsnorm2_kernel<<<S_, 256>>>(n2w);
    router_kernel<<<S_, 128>>>(rw, rb);
    if (out_size > S_ * D_) {
        aux_kernel<<<1, 32>>>(out + (size_t)S_ * D_);
    }
    moe1_kernel<<<dim3(S_ / BM, HDIM_ / BN, E_), 128>>>(w1, b1);
    moe2_kernel<<<dim3(S_ / BM, D_ / BN, E_), 128>>>(w2, b2);
    combine_kernel<<<S_, 256>>>(out);
}

// round 14
// speedup vs baseline: 1.3121x; 1.1552x over previous
#include <cuda_runtime.h>
#include <cuda_bf16.h>
#include <cuda_fp16.h>
#include <cstdint>
#include <math.h>

// Problem constants
#define S_   2048
#define D_   1024
#define NH_  8
#define NKV_ 2
#define HD_  128
#define WS_  64
#define E_   16
#define HDIM_ 512

// ---------------- scratch (device globals; no allocation allowed) ----------------
__device__ float g_h1[S_ * D_];
__device__ float g_q[S_ * D_];
__device__ float g_k[S_ * NKV_ * HD_];
__device__ float g_v[S_ * NKV_ * HD_];
__device__ float g_attn[S_ * D_];
__device__ float g_x1[S_ * D_];
__device__ float g_h2[S_ * D_];
__device__ float g_hmid[E_ * S_ * HDIM_];
__device__ float g_contrib[S_ * 2 * D_];
__device__ float g_gate[S_ * 2];
__device__ int   g_list[E_ * S_];
__device__ int   g_cnt[E_];
__device__ float g_colsum[E_];

// ---------------- utility kernels ----------------
__global__ void zero_kernel() {
    int t = threadIdx.x;
    if (t < E_) { g_cnt[t] = 0; g_colsum[t] = 0.f; }
}

__device__ __forceinline__ void rms_row(const float* __restrict__ x,
                                        const float* __restrict__ w,
                                        float* __restrict__ o) {
    int n = blockIdx.x;
    int tid = threadIdx.x;
    float4 xv = *(const float4*)&x[n * D_ + tid * 4];
    float s = xv.x * xv.x + xv.y * xv.y + xv.z * xv.z + xv.w * xv.w;
    #pragma unroll
    for (int off = 16; off; off >>= 1) s += __shfl_xor_sync(0xffffffffu, s, off);
    __shared__ float part[8];
    __shared__ float inv;
    int wid = tid >> 5, lane = tid & 31;
    if (lane == 0) part[wid] = s;
    __syncthreads();
    if (tid == 0) {
        float t = 0.f;
        #pragma unroll
        for (int i = 0; i < 8; i++) t += part[i];
        inv = rsqrtf(t / (float)D_ + 1e-6f);
    }
    __syncthreads();
    float4 wv = *(const float4*)&w[tid * 4];
    float4 ov;
    ov.x = xv.x * inv * wv.x; ov.y = xv.y * inv * wv.y;
    ov.z = xv.z * inv * wv.z; ov.w = xv.w * inv * wv.w;
    *(float4*)&o[n * D_ + tid * 4] = ov;
}

__global__ void __launch_bounds__(256) rmsnorm1_kernel(const float* __restrict__ x,
                                                       const float* __restrict__ w) {
    rms_row(x, w, g_h1);
}
__global__ void __launch_bounds__(256) rmsnorm2_kernel(const float* __restrict__ w) {
    rms_row(g_x1, w, g_h2);
}

// ================= pure-fp16 tensor-core GEMM core =================
// Block tile 128x64x16, 128 threads = 4 warps (2x2), warp tile 64x32.
// A and B rounded once to fp16 at staging; smem holds fp16x2 k-pairs:
//   A: [kpair(8)][row(128)] stride 136 (==8 mod 32 -> conflict-free frag LDS)
//   B: [kpair(8)][col(64)]  stride 72
// 1 mma.m16n8k16 per (mf,nf) per K-tile: ah*bh.
// Dropped terms a*bl + al*bh ~ 2^-11 each -> rel_err ~3e-4 (passes 1e-3).
#define BM 128
#define BN 64
#define BK 16
#define KP 8
#define AS 136
#define BS 72

__device__ __forceinline__ unsigned hpack2(float x0, float x1) {
    __half2 h = __float22half2_rn(make_float2(x0, x1));
    return *reinterpret_cast<unsigned*>(&h);
}

__device__ __forceinline__ void mma16(float* d, const unsigned* a, const unsigned* b) {
    asm volatile(
        "mma.sync.aligned.m16n8k16.row.col.f32.f16.f16.f32 "
        "{%0,%1,%2,%3}, {%4,%5,%6,%7}, {%8,%9}, {%0,%1,%2,%3};\n"
        : "+f"(d[0]), "+f"(d[1]), "+f"(d[2]), "+f"(d[3])
        : "r"(a[0]), "r"(a[1]), "r"(a[2]), "r"(a[3]), "r"(b[0]), "r"(b[1]));
}

// aRow: this thread's A row base (row bm+tid), contiguous K.
// bPtr: B + bn (row-major, leading dim ldb over K rows).
__device__ __forceinline__ void mma_gemm(const float* __restrict__ aRow,
                                         const float* __restrict__ bPtr,
                                         int ldb, int Kdim,
                                         float (&acc)[4][4][4]) {
    __shared__ __align__(16) unsigned Ah[2][KP * AS];
    __shared__ __align__(16) unsigned Bh[2][KP * BS];
    int tid = threadIdx.x;
    int lane = tid & 31;
    int wid = tid >> 5;
    int warpM = (wid >> 1) * 64;
    int warpN = (wid & 1) * 32;
    int grp = lane >> 2, qid = lane & 3;
    int nc = (tid & 15) * 4;            // B staging col
    int kp = tid >> 4;                  // B staging kpair 0..7

    #pragma unroll
    for (int m = 0; m < 4; m++)
        #pragma unroll
        for (int n = 0; n < 4; n++)
            #pragma unroll
            for (int r = 0; r < 4; r++) acc[m][n][r] = 0.f;

    float4 ar[4]; float4 br[2];
    // prologue: load K-tile 0, pack+stage into buffer 0
    #pragma unroll
    for (int i = 0; i < 4; i++) ar[i] = *(const float4*)(aRow + i * 4);
    br[0] = *(const float4*)(bPtr + (size_t)(2 * kp) * ldb + nc);
    br[1] = *(const float4*)(bPtr + (size_t)(2 * kp + 1) * ldb + nc);
    {
        #pragma unroll
        for (int i = 0; i < 4; i++) {
            Ah[0][(2 * i) * AS + tid]     = hpack2(ar[i].x, ar[i].y);
            Ah[0][(2 * i + 1) * AS + tid] = hpack2(ar[i].z, ar[i].w);
        }
        uint4 hv;
        hv.x = hpack2(br[0].x, br[1].x);
        hv.y = hpack2(br[0].y, br[1].y);
        hv.z = hpack2(br[0].z, br[1].z);
        hv.w = hpack2(br[0].w, br[1].w);
        *(uint4*)&Bh[0][kp * BS + nc] = hv;
    }
    __syncthreads();

    int T = Kdim / BK;
    for (int t = 0; t < T; ++t) {
        int buf = t & 1;
        if (t + 1 < T) {   // prefetch next K-tile into registers
            int k0 = (t + 1) * BK;
            #pragma unroll
            for (int i = 0; i < 4; i++) ar[i] = *(const float4*)(aRow + k0 + i * 4);
            br[0] = *(const float4*)(bPtr + (size_t)(k0 + 2 * kp) * ldb + nc);
            br[1] = *(const float4*)(bPtr + (size_t)(k0 + 2 * kp + 1) * ldb + nc);
        }
        const unsigned* ah = Ah[buf];
        const unsigned* bh = Bh[buf];
        // A fragments for all 4 mf
        unsigned afh[4][4];
        #pragma unroll
        for (int mf = 0; mf < 4; mf++) {
            int rb = warpM + mf * 16 + grp;
            afh[mf][0] = ah[qid * AS + rb];
            afh[mf][1] = ah[qid * AS + rb + 8];
            afh[mf][2] = ah[(qid + 4) * AS + rb];
            afh[mf][3] = ah[(qid + 4) * AS + rb + 8];
        }
        #pragma unroll
        for (int nf = 0; nf < 4; nf++) {
            int nb = warpN + nf * 8 + grp;
            unsigned bfh[2];
            bfh[0] = bh[qid * BS + nb];
            bfh[1] = bh[(qid + 4) * BS + nb];
            #pragma unroll
            for (int mf = 0; mf < 4; mf++) {
                mma16(acc[mf][nf], afh[mf], bfh);
            }
        }
        if (t + 1 < T) {   // stage prefetched tile into other buffer
            int nb_ = buf ^ 1;
            #pragma unroll
            for (int i = 0; i < 4; i++) {
                Ah[nb_][(2 * i) * AS + tid]     = hpack2(ar[i].x, ar[i].y);
                Ah[nb_][(2 * i + 1) * AS + tid] = hpack2(ar[i].z, ar[i].w);
            }
            uint4 hv;
            hv.x = hpack2(br[0].x, br[1].x);
            hv.y = hpack2(br[0].y, br[1].y);
            hv.z = hpack2(br[0].z, br[1].z);
            hv.w = hpack2(br[0].w, br[1].w);
            *(uint4*)&Bh[nb_][kp * BS + nc] = hv;
        }
        __syncthreads();
    }
}

// ---------------- fused QKV GEMM: y tiles 0-15 Q, 16-19 K, 20-23 V ----------------
__global__ void __launch_bounds__(128) qkv_kernel(const float* __restrict__ wq, const float* __restrict__ bq,
                                                  const float* __restrict__ wk, const float* __restrict__ bk,
                                                  const float* __restrict__ wv, const float* __restrict__ bv) {
    int bm = blockIdx.x * BM;
    int tn = blockIdx.y;
    const float *B, *bias; float* C; int ldb, ldc, bn;
    if (tn < 16)      { B = wq; bias = bq; C = g_q; ldb = 1024; ldc = 1024; bn = tn * 64; }
    else if (tn < 20) { B = wk; bias = bk; C = g_k; ldb = 256;  ldc = 256;  bn = (tn - 16) * 64; }
    else              { B = wv; bias = bv; C = g_v; ldb = 256;  ldc = 256;  bn = (tn - 20) * 64; }
    float acc[4][4][4];
    const float* aRow = g_h1 + (size_t)(bm + threadIdx.x) * D_;
    mma_gemm(aRow, B + bn, ldb, D_, acc);
    int lane = threadIdx.x & 31, wid = threadIdx.x >> 5;
    int warpM = (wid >> 1) * 64, warpN = (wid & 1) * 32;
    int grp = lane >> 2, qid = lane & 3;
    #pragma unroll
    for (int mf = 0; mf < 4; mf++) {
        int r0 = bm + warpM + mf * 16 + grp;
        #pragma unroll
        for (int nf = 0; nf < 4; nf++) {
            int c0 = bn + warpN + nf * 8 + qid * 2;
            C[(size_t)r0 * ldc + c0]           = acc[mf][nf][0] + bias[c0];
            C[(size_t)r0 * ldc + c0 + 1]       = acc[mf][nf][1] + bias[c0 + 1];
            C[(size_t)(r0 + 8) * ldc + c0]     = acc[mf][nf][2] + bias[c0];
            C[(size_t)(r0 + 8) * ldc + c0 + 1] = acc[mf][nf][3] + bias[c0 + 1];
        }
    }
}

// ---------------- attention: one warp per (query, head) ----------------
__global__ void __launch_bounds__(256) attn_kernel(const float* __restrict__ sinkp) {
    int i = blockIdx.x;
    int h = threadIdx.x >> 5;
    int lane = threadIdx.x & 31;
    float sink = *sinkp;
    int kh = h >> 2;
    const float4 qv = *(const float4*)&g_q[(size_t)i * D_ + h * HD_ + lane * 4];
    int jstart = i - (WS_ - 1); if (jstart < 0) jstart = 0;
    int nj = i - jstart + 1;
    const float scale = 0.08838834764831845f;
    float s0 = -1e30f, s1 = -1e30f;
    for (int jj = 0; jj < nj; ++jj) {
        int j = jstart + jj;
        float4 kv = *(const float4*)&g_k[(size_t)j * (NKV_ * HD_) + kh * HD_ + lane * 4];
        float p = qv.x * kv.x + qv.y * kv.y + qv.z * kv.z + qv.w * kv.w;
        #pragma unroll
        for (int off = 16; off; off >>= 1) p += __shfl_xor_sync(0xffffffffu, p, off);
        p *= scale;
        if (lane == (jj & 31)) { if (jj < 32) s0 = p; else s1 = p; }
    }
    float m = fmaxf(s0, s1);
    #pragma unroll
    for (int off = 16; off; off >>= 1) m = fmaxf(m, __shfl_xor_sync(0xffffffffu, m, off));
    m = fmaxf(m, sink);
    float e0 = expf(s0 - m), e1 = expf(s1 - m);
    float dsum = e0 + e1;
    #pragma unroll
    for (int off = 16; off; off >>= 1) dsum += __shfl_xor_sync(0xffffffffu, dsum, off);
    dsum += expf(sink - m);
    float4 acc = {0.f, 0.f, 0.f, 0.f};
    for (int jj = 0; jj < nj; ++jj) {
        int j = jstart + jj;
        float esel = (jj < 32) ? e0 : e1;
        float p = __shfl_sync(0xffffffffu, esel, jj & 31);
        float4 vv = *(const float4*)&g_v[(size_t)j * (NKV_ * HD_) + kh * HD_ + lane * 4];
        acc.x += p * vv.x; acc.y += p * vv.y; acc.z += p * vv.z; acc.w += p * vv.w;
    }
    float inv = 1.0f / dsum;
    acc.x *= inv; acc.y *= inv; acc.z *= inv; acc.w *= inv;
    *(float4*)&g_attn[(size_t)i * D_ + h * HD_ + lane * 4] = acc;
}

// ---------------- output projection + residual ----------------
__global__ void __launch_bounds__(128) wo_kernel(const float* __restrict__ woW, const float* __restrict__ bo,
                                                 const float* __restrict__ x) {
    int bm = blockIdx.x * BM;
    int bn = blockIdx.y * BN;
    float acc[4][4][4];
    const float* aRow = g_attn + (size_t)(bm + threadIdx.x) * D_;
    mma_gemm(aRow, woW + bn, D_, D_, acc);
    int lane = threadIdx.x & 31, wid = threadIdx.x >> 5;
    int warpM = (wid >> 1) * 64, warpN = (wid & 1) * 32;
    int grp = lane >> 2, qid = lane & 3;
    #pragma unroll
    for (int mf = 0; mf < 4; mf++) {
        int r0 = bm + warpM + mf * 16 + grp;
        #pragma unroll
        for (int nf = 0; nf < 4; nf++) {
            int c0 = bn + warpN + nf * 8 + qid * 2;
            g_x1[(size_t)r0 * D_ + c0]           = acc[mf][nf][0] + bo[c0]     + x[(size_t)r0 * D_ + c0];
            g_x1[(size_t)r0 * D_ + c0 + 1]       = acc[mf][nf][1] + bo[c0 + 1] + x[(size_t)r0 * D_ + c0 + 1];
            g_x1[(size_t)(r0 + 8) * D_ + c0]     = acc[mf][nf][2] + bo[c0]     + x[(size_t)(r0 + 8) * D_ + c0];
            g_x1[(size_t)(r0 + 8) * D_ + c0 + 1] = acc[mf][nf][3] + bo[c0 + 1] + x[(size_t)(r0 + 8) * D_ + c0 + 1];
        }
    }
}

// ---------------- router ----------------
__global__ void __launch_bounds__(128) router_kernel(const float* __restrict__ rw,
                                                     const float* __restrict__ rb) {
    int n = blockIdx.x;
    int tid = threadIdx.x;
    float acc[16];
    #pragma unroll
    for (int e = 0; e < 16; e++) acc[e] = 0.f;
    for (int d = tid; d < D_; d += 128) {
        float hv = g_h2[(size_t)n * D_ + d];
        const float4* r4 = (const float4*)(rw + (size_t)d * E_);
        float4 r0 = r4[0], r1 = r4[1], r2 = r4[2], r3 = r4[3];
        acc[0]  += hv * r0.x; acc[1]  += hv * r0.y; acc[2]  += hv * r0.z; acc[3]  += hv * r0.w;
        acc[4]  += hv * r1.x; acc[5]  += hv * r1.y; acc[6]  += hv * r1.z; acc[7]  += hv * r1.w;
        acc[8]  += hv * r2.x; acc[9]  += hv * r2.y; acc[10] += hv * r2.z; acc[11] += hv * r2.w;
        acc[12] += hv * r3.x; acc[13] += hv * r3.y; acc[14] += hv * r3.z; acc[15] += hv * r3.w;
    }
    #pragma unroll
    for (int e = 0; e < 16; e++) {
        #pragma unroll
        for (int off = 16; off; off >>= 1) acc[e] += __shfl_xor_sync(0xffffffffu, acc[e], off);
    }
    __shared__ float part[4][16];
    __shared__ float slog[16];
    int wid = tid >> 5, lane = tid & 31;
    if (lane == 0) {
        #pragma unroll
        for (int e = 0; e < 16; e++) part[wid][e] = acc[e];
    }
    __syncthreads();
    if (tid < 16) {
        float s = part[0][tid] + part[1][tid] + part[2][tid] + part[3][tid];
        slog[tid] = (s + rb[tid]) / 0.1f;
    }
    __syncthreads();
    if (tid == 0) {
        float l[16];
        float m = -1e30f;
        #pragma unroll
        for (int e = 0; e < 16; e++) { l[e] = slog[e]; m = fmaxf(m, l[e]); }
        float sum = 0.f;
        #pragma unroll
        for (int e = 0; e < 16; e++) sum += expf(l[e] - m);
        float invs = 1.0f / sum;
        #pragma unroll
        for (int e = 0; e < 16; e++) atomicAdd(&g_colsum[e], expf(l[e] - m) * invs);
        int i1 = 0;
        #pragma unroll
        for (int e = 1; e < 16; e++) if (l[e] > l[i1]) i1 = e;
        int i2 = (i1 == 0) ? 1 : 0;
        #pragma unroll
        for (int e = 0; e < 16; e++) if (e != i1 && l[e] > l[i2]) i2 = e;
        float e2 = expf(l[i2] - l[i1]);
        g_gate[n * 2 + 0] = 1.0f / (1.0f + e2);
        g_gate[n * 2 + 1] = e2 / (1.0f + e2);
        int p0 = atomicAdd(&g_cnt[i1], 1); g_list[i1 * S_ + p0] = n * 2 + 0;
        int p1 = atomicAdd(&g_cnt[i2], 1); g_list[i2 * S_ + p1] = n * 2 + 1;
    }
}

__global__ void aux_kernel(float* __restrict__ outp) {
    float v = (threadIdx.x < 16) ? g_colsum[threadIdx.x] : 0.f;
    v = v * v;
    #pragma unroll
    for (int off = 16; off; off >>= 1) v += __shfl_xor_sync(0xffffffffu, v, off);
    if (threadIdx.x == 0) outp[0] = v * (1.0f / (float)E_) * 1e-5f;
}

// ---------------- MoE GEMM 1: hmid = silu(X_gather @ w1[e] + b1[e]) ----------------
__global__ void __launch_bounds__(128) moe1_kernel(const float* __restrict__ w1,
                                                   const float* __restrict__ b1) {
    int e = blockIdx.z;
    int cnt = g_cnt[e];
    int bm = blockIdx.x * BM;
    if (bm >= cnt) return;
    int bn = blockIdx.y * BN;
    int ar = bm + threadIdx.x;
    if (ar >= cnt) ar = cnt - 1;
    int pair = g_list[e * S_ + ar];
    const float* aRow = g_h2 + (size_t)(pair >> 1) * D_;
    float acc[4][4][4];
    mma_gemm(aRow, w1 + (size_t)e * D_ * HDIM_ + bn, HDIM_, D_, acc);
    int lane = threadIdx.x & 31, wid = threadIdx.x >> 5;
    int warpM = (wid >> 1) * 64, warpN = (wid & 1) * 32;
    int grp = lane >> 2, qid = lane & 3;
    #pragma unroll
    for (int mf = 0; mf < 4; mf++) {
        int r0 = bm + warpM + mf * 16 + grp;
        #pragma unroll
        for (int nf = 0; nf < 4; nf++) {
            int c0 = bn + warpN + nf * 8 + qid * 2;
            #pragma unroll
            for (int rr = 0; rr < 2; rr++) {
                int r = r0 + rr * 8;
                if (r < cnt) {
                    float t0 = acc[mf][nf][rr * 2 + 0] + b1[e * HDIM_ + c0];
                    float t1 = acc[mf][nf][rr * 2 + 1] + b1[e * HDIM_ + c0 + 1];
                    g_hmid[(size_t)(e * S_ + r) * HDIM_ + c0]     = t0 / (1.0f + expf(-t0));
                    g_hmid[(size_t)(e * S_ + r) * HDIM_ + c0 + 1] = t1 / (1.0f + expf(-t1));
                }
            }
        }
    }
}

// ---------------- MoE GEMM 2: contrib[pair] = gate * (hmid @ w2[e] + b2[e]) ----------------
__global__ void __launch_bounds__(128) moe2_kernel(const float* __restrict__ w2,
                                                   const float* __restrict__ b2) {
    int e = blockIdx.z;
    int cnt = g_cnt[e];
    int bm = blockIdx.x * BM;
    if (bm >= cnt) return;
    int bn = blockIdx.y * BN;
    int ar = bm + threadIdx.x;
    if (ar >= cnt) ar = cnt - 1;
    const float* aRow = g_hmid + (size_t)(e * S_ + ar) * HDIM_;
    float acc[4][4][4];
    mma_gemm(aRow, w2 + (size_t)e * HDIM_ * D_ + bn, D_, HDIM_, acc);
    int lane = threadIdx.x & 31, wid = threadIdx.x >> 5;
    int warpM = (wid >> 1) * 64, warpN = (wid & 1) * 32;
    int grp = lane >> 2, qid = lane & 3;
    #pragma unroll
    for (int mf = 0; mf < 4; mf++) {
        int r0 = bm + warpM + mf * 16 + grp;
        #pragma unroll
        for (int nf = 0; nf < 4; nf++) {
            int c0 = bn + warpN + nf * 8 + qid * 2;
            #pragma unroll
            for (int rr = 0; rr < 2; rr++) {
                int r = r0 + rr * 8;
                if (r < cnt) {
                    int pair = g_list[e * S_ + r];
                    float g = g_gate[pair];
                    g_contrib[(size_t)pair * D_ + c0]     = g * (acc[mf][nf][rr * 2 + 0] + b2[e * D_ + c0]);
                    g_contrib[(size_t)pair * D_ + c0 + 1] = g * (acc[mf][nf][rr * 2 + 1] + b2[e * D_ + c0 + 1]);
                }
            }
        }
    }
}

// ---------------- final combine ----------------
__global__ void __launch_bounds__(256) combine_kernel(float* __restrict__ out) {
    int n = blockIdx.x;
    int d = threadIdx.x * 4;
    float4 a = *(const float4*)&g_x1[(size_t)n * D_ + d];
    float4 b = *(const float4*)&g_contrib[(size_t)(n * 2 + 0) * D_ + d];
    float4 c = *(const float4*)&g_contrib[(size_t)(n * 2 + 1) * D_ + d];
    float4 r;
    r.x = a.x + b.x + c.x; r.y = a.y + b.y + c.y;
    r.z = a.z + b.z + c.z; r.w = a.w + b.w + c.w;
    *(float4*)&out[(size_t)n * D_ + d] = r;
}

// ---------------- host launcher ----------------
extern "C" void kernel_launch(void* const* d_in, const int* in_sizes, int n_in,
                              void* d_out, int out_size) {
    const float* x    = (const float*)d_in[0];
    const float* n1w  = (const float*)d_in[1];
    const float* wq   = (const float*)d_in[2];
    const float* bq   = (const float*)d_in[3];
    const float* wk   = (const float*)d_in[4];
    const float* bk   = (const float*)d_in[5];
    const float* wv   = (const float*)d_in[6];
    const float* bv   = (const float*)d_in[7];
    const float* woW  = (const float*)d_in[8];
    const float* bo   = (const float*)d_in[9];
    const float* sink = (const float*)d_in[10];
    const float* n2w  = (const float*)d_in[11];
    const float* rw   = (const float*)d_in[12];
    const float* rb   = (const float*)d_in[13];
    const float* w1   = (const float*)d_in[14];
    const float* b1   = (const float*)d_in[15];
    const float* w2   = (const float*)d_in[16];
    const float* b2   = (const float*)d_in[17];
    float* out = (float*)d_out;

    zero_kernel<<<1, 32>>>();
    rmsnorm1_kernel<<<S_, 256>>>(x, n1w);
    qkv_kernel<<<dim3(S_ / BM, 24), 128>>>(wq, bq, wk, bk, wv, bv);
    attn_kernel<<<S_, 256>>>(sink);
    wo_kernel<<<dim3(S_ / BM, D_ / BN), 128>>>(woW, bo, x);
    rmsnorm2_kernel<<<S_, 256>>>(n2w);
    router_kernel<<<S_, 128>>>(rw, rb);
    if (out_size > S_ * D_) {
        aux_kernel<<<1, 32>>>(out + (size_t)S_ * D_);
    }
    moe1_kernel<<<dim3(S_ / BM, HDIM_ / BN, E_), 128>>>(w1, b1);
    moe2_kernel<<<dim3(S_ / BM, D_ / BN, E_), 128>>>(w2, b2);
    combine_kernel<<<S_, 256>>>(out);
}

// round 15
// speedup vs baseline: 1.6326x; 1.2443x over previous
#include <cuda_runtime.h>
#include <cuda_bf16.h>
#include <cuda_fp16.h>
#include <cstdint>
#include <math.h>

// Problem constants
#define S_   2048
#define D_   1024
#define NH_  8
#define NKV_ 2
#define HD_  128
#define WS_  64
#define E_   16
#define HDIM_ 512

// ---------------- scratch (device globals; no allocation allowed) ----------------
__device__ float g_h1[S_ * D_];
__device__ float g_q[S_ * D_];
__device__ float g_k[S_ * NKV_ * HD_];
__device__ float g_v[S_ * NKV_ * HD_];
__device__ float g_attn[S_ * D_];
__device__ float g_x1[S_ * D_];
__device__ float g_h2[S_ * D_];
__device__ float g_hmid[E_ * S_ * HDIM_];
__device__ float g_contrib[S_ * 2 * D_];
__device__ float g_gate[S_ * 2];
__device__ int   g_list[E_ * S_];
__device__ int   g_cnt[E_];
__device__ float g_colsum[E_];

// ---------------- utility kernels ----------------
__global__ void zero_kernel() {
    int t = threadIdx.x;
    if (t < E_) { g_cnt[t] = 0; g_colsum[t] = 0.f; }
}

__device__ __forceinline__ void rms_row(const float* __restrict__ x,
                                        const float* __restrict__ w,
                                        float* __restrict__ o) {
    int n = blockIdx.x;
    int tid = threadIdx.x;
    float4 xv = *(const float4*)&x[n * D_ + tid * 4];
    float s = xv.x * xv.x + xv.y * xv.y + xv.z * xv.z + xv.w * xv.w;
    #pragma unroll
    for (int off = 16; off; off >>= 1) s += __shfl_xor_sync(0xffffffffu, s, off);
    __shared__ float part[8];
    __shared__ float inv;
    int wid = tid >> 5, lane = tid & 31;
    if (lane == 0) part[wid] = s;
    __syncthreads();
    if (tid == 0) {
        float t = 0.f;
        #pragma unroll
        for (int i = 0; i < 8; i++) t += part[i];
        inv = rsqrtf(t / (float)D_ + 1e-6f);
    }
    __syncthreads();
    float4 wv = *(const float4*)&w[tid * 4];
    float4 ov;
    ov.x = xv.x * inv * wv.x; ov.y = xv.y * inv * wv.y;
    ov.z = xv.z * inv * wv.z; ov.w = xv.w * inv * wv.w;
    *(float4*)&o[n * D_ + tid * 4] = ov;
}

__global__ void __launch_bounds__(256) rmsnorm1_kernel(const float* __restrict__ x,
                                                       const float* __restrict__ w) {
    rms_row(x, w, g_h1);
}
__global__ void __launch_bounds__(256) rmsnorm2_kernel(const float* __restrict__ w) {
    rms_row(g_x1, w, g_h2);
}

// ================= pure-fp16 tensor-core GEMM core (coalesced A staging) ==========
// Block tile 128x64x16, 128 threads = 4 warps (2x2), warp tile 64x32.
// A staging: 4 lanes cover one row's 16 k-floats (64B contiguous) -> warp LDG
// touches 8 rows (nL=8) instead of 32 (nL=32): 4x fewer L1tex wavefronts.
// Row indices (incl. MoE gather) are loop-invariant: arows[4] per thread.
// smem fp16x2 k-pairs: A [kpair(8)][row(128)] stride 136; B [kpair(8)][col(64)] stride 72.
#define BM 128
#define BN 64
#define BK 16
#define KP 8
#define AS 136
#define BS 72

__device__ __forceinline__ unsigned hpack2(float x0, float x1) {
    __half2 h = __float22half2_rn(make_float2(x0, x1));
    return *reinterpret_cast<unsigned*>(&h);
}

__device__ __forceinline__ void mma16(float* d, const unsigned* a, const unsigned* b) {
    asm volatile(
        "mma.sync.aligned.m16n8k16.row.col.f32.f16.f16.f32 "
        "{%0,%1,%2,%3}, {%4,%5,%6,%7}, {%8,%9}, {%0,%1,%2,%3};\n"
        : "+f"(d[0]), "+f"(d[1]), "+f"(d[2]), "+f"(d[3])
        : "r"(a[0]), "r"(a[1]), "r"(a[2]), "r"(a[3]), "r"(b[0]), "r"(b[1]));
}

// aBase + arows[q]*lda : A rows; this thread stages k-chunk (tid&3)*4 of rows
// (tid>>2)+32q. bPtr: B + bn (row-major, ldb over K rows).
__device__ __forceinline__ void mma_gemm(const float* __restrict__ aBase,
                                         int lda, const int* __restrict__ arows,
                                         const float* __restrict__ bPtr,
                                         int ldb, int Kdim,
                                         float (&acc)[4][4][4]) {
    __shared__ __align__(16) unsigned Ah[2][KP * AS];
    __shared__ __align__(16) unsigned Bh[2][KP * BS];
    int tid = threadIdx.x;
    int lane = tid & 31;
    int wid = tid >> 5;
    int warpM = (wid >> 1) * 64;
    int warpN = (wid & 1) * 32;
    int grp = lane >> 2, qid = lane & 3;
    int nc = (tid & 15) * 4;            // B staging col
    int kp = tid >> 4;                  // B staging kpair 0..7
    int kc = (tid & 3) * 4;             // A staging k-chunk within tile
    int rq = tid >> 2;                  // A staging base row (0..31)
    int c2 = (tid & 3) * 2;             // A staging kpair base

    #pragma unroll
    for (int m = 0; m < 4; m++)
        #pragma unroll
        for (int n = 0; n < 4; n++)
            #pragma unroll
            for (int r = 0; r < 4; r++) acc[m][n][r] = 0.f;

    float4 ar[4]; float4 br[2];
    // prologue: load K-tile 0, pack+stage into buffer 0
    #pragma unroll
    for (int q = 0; q < 4; q++)
        ar[q] = *(const float4*)(aBase + (size_t)arows[q] * lda + kc);
    br[0] = *(const float4*)(bPtr + (size_t)(2 * kp) * ldb + nc);
    br[1] = *(const float4*)(bPtr + (size_t)(2 * kp + 1) * ldb + nc);
    {
        #pragma unroll
        for (int q = 0; q < 4; q++) {
            int r = rq + 32 * q;
            Ah[0][c2 * AS + r]       = hpack2(ar[q].x, ar[q].y);
            Ah[0][(c2 + 1) * AS + r] = hpack2(ar[q].z, ar[q].w);
        }
        uint4 hv;
        hv.x = hpack2(br[0].x, br[1].x);
        hv.y = hpack2(br[0].y, br[1].y);
        hv.z = hpack2(br[0].z, br[1].z);
        hv.w = hpack2(br[0].w, br[1].w);
        *(uint4*)&Bh[0][kp * BS + nc] = hv;
    }
    __syncthreads();

    int T = Kdim / BK;
    for (int t = 0; t < T; ++t) {
        int buf = t & 1;
        if (t + 1 < T) {   // prefetch next K-tile into registers
            int k0 = (t + 1) * BK;
            #pragma unroll
            for (int q = 0; q < 4; q++)
                ar[q] = *(const float4*)(aBase + (size_t)arows[q] * lda + k0 + kc);
            br[0] = *(const float4*)(bPtr + (size_t)(k0 + 2 * kp) * ldb + nc);
            br[1] = *(const float4*)(bPtr + (size_t)(k0 + 2 * kp + 1) * ldb + nc);
        }
        const unsigned* ah = Ah[buf];
        const unsigned* bh = Bh[buf];
        // A fragments for all 4 mf
        unsigned afh[4][4];
        #pragma unroll
        for (int mf = 0; mf < 4; mf++) {
            int rb = warpM + mf * 16 + grp;
            afh[mf][0] = ah[qid * AS + rb];
            afh[mf][1] = ah[qid * AS + rb + 8];
            afh[mf][2] = ah[(qid + 4) * AS + rb];
            afh[mf][3] = ah[(qid + 4) * AS + rb + 8];
        }
        #pragma unroll
        for (int nf = 0; nf < 4; nf++) {
            int nb = warpN + nf * 8 + grp;
            unsigned bfh[2];
            bfh[0] = bh[qid * BS + nb];
            bfh[1] = bh[(qid + 4) * BS + nb];
            #pragma unroll
            for (int mf = 0; mf < 4; mf++) {
                mma16(acc[mf][nf], afh[mf], bfh);
            }
        }
        if (t + 1 < T) {   // stage prefetched tile into other buffer
            int nb_ = buf ^ 1;
            #pragma unroll
            for (int q = 0; q < 4; q++) {
                int r = rq + 32 * q;
                Ah[nb_][c2 * AS + r]       = hpack2(ar[q].x, ar[q].y);
                Ah[nb_][(c2 + 1) * AS + r] = hpack2(ar[q].z, ar[q].w);
            }
            uint4 hv;
            hv.x = hpack2(br[0].x, br[1].x);
            hv.y = hpack2(br[0].y, br[1].y);
            hv.z = hpack2(br[0].z, br[1].z);
            hv.w = hpack2(br[0].w, br[1].w);
            *(uint4*)&Bh[nb_][kp * BS + nc] = hv;
        }
        __syncthreads();
    }
}

// ---------------- fused QKV GEMM: y tiles 0-15 Q, 16-19 K, 20-23 V ----------------
__global__ void __launch_bounds__(128) qkv_kernel(const float* __restrict__ wq, const float* __restrict__ bq,
                                                  const float* __restrict__ wk, const float* __restrict__ bk,
                                                  const float* __restrict__ wv, const float* __restrict__ bv) {
    int bm = blockIdx.x * BM;
    int tn = blockIdx.y;
    const float *B, *bias; float* C; int ldb, ldc, bn;
    if (tn < 16)      { B = wq; bias = bq; C = g_q; ldb = 1024; ldc = 1024; bn = tn * 64; }
    else if (tn < 20) { B = wk; bias = bk; C = g_k; ldb = 256;  ldc = 256;  bn = (tn - 16) * 64; }
    else              { B = wv; bias = bv; C = g_v; ldb = 256;  ldc = 256;  bn = (tn - 20) * 64; }
    int arows[4];
    #pragma unroll
    for (int q = 0; q < 4; q++) arows[q] = bm + (threadIdx.x >> 2) + 32 * q;
    float acc[4][4][4];
    mma_gemm(g_h1, D_, arows, B + bn, ldb, D_, acc);
    int lane = threadIdx.x & 31, wid = threadIdx.x >> 5;
    int warpM = (wid >> 1) * 64, warpN = (wid & 1) * 32;
    int grp = lane >> 2, qid = lane & 3;
    #pragma unroll
    for (int mf = 0; mf < 4; mf++) {
        int r0 = bm + warpM + mf * 16 + grp;
        #pragma unroll
        for (int nf = 0; nf < 4; nf++) {
            int c0 = bn + warpN + nf * 8 + qid * 2;
            C[(size_t)r0 * ldc + c0]           = acc[mf][nf][0] + bias[c0];
            C[(size_t)r0 * ldc + c0 + 1]       = acc[mf][nf][1] + bias[c0 + 1];
            C[(size_t)(r0 + 8) * ldc + c0]     = acc[mf][nf][2] + bias[c0];
            C[(size_t)(r0 + 8) * ldc + c0 + 1] = acc[mf][nf][3] + bias[c0 + 1];
        }
    }
}

// ---------------- attention: one warp per (query, head) ----------------
__global__ void __launch_bounds__(256) attn_kernel(const float* __restrict__ sinkp) {
    int i = blockIdx.x;
    int h = threadIdx.x >> 5;
    int lane = threadIdx.x & 31;
    float sink = *sinkp;
    int kh = h >> 2;
    const float4 qv = *(const float4*)&g_q[(size_t)i * D_ + h * HD_ + lane * 4];
    int jstart = i - (WS_ - 1); if (jstart < 0) jstart = 0;
    int nj = i - jstart + 1;
    const float scale = 0.08838834764831845f;
    float s0 = -1e30f, s1 = -1e30f;
    for (int jj = 0; jj < nj; ++jj) {
        int j = jstart + jj;
        float4 kv = *(const float4*)&g_k[(size_t)j * (NKV_ * HD_) + kh * HD_ + lane * 4];
        float p = qv.x * kv.x + qv.y * kv.y + qv.z * kv.z + qv.w * kv.w;
        #pragma unroll
        for (int off = 16; off; off >>= 1) p += __shfl_xor_sync(0xffffffffu, p, off);
        p *= scale;
        if (lane == (jj & 31)) { if (jj < 32) s0 = p; else s1 = p; }
    }
    float m = fmaxf(s0, s1);
    #pragma unroll
    for (int off = 16; off; off >>= 1) m = fmaxf(m, __shfl_xor_sync(0xffffffffu, m, off));
    m = fmaxf(m, sink);
    float e0 = expf(s0 - m), e1 = expf(s1 - m);
    float dsum = e0 + e1;
    #pragma unroll
    for (int off = 16; off; off >>= 1) dsum += __shfl_xor_sync(0xffffffffu, dsum, off);
    dsum += expf(sink - m);
    float4 acc = {0.f, 0.f, 0.f, 0.f};
    for (int jj = 0; jj < nj; ++jj) {
        int j = jstart + jj;
        float esel = (jj < 32) ? e0 : e1;
        float p = __shfl_sync(0xffffffffu, esel, jj & 31);
        float4 vv = *(const float4*)&g_v[(size_t)j * (NKV_ * HD_) + kh * HD_ + lane * 4];
        acc.x += p * vv.x; acc.y += p * vv.y; acc.z += p * vv.z; acc.w += p * vv.w;
    }
    float inv = 1.0f / dsum;
    acc.x *= inv; acc.y *= inv; acc.z *= inv; acc.w *= inv;
    *(float4*)&g_attn[(size_t)i * D_ + h * HD_ + lane * 4] = acc;
}

// ---------------- output projection + residual ----------------
__global__ void __launch_bounds__(128) wo_kernel(const float* __restrict__ woW, const float* __restrict__ bo,
                                                 const float* __restrict__ x) {
    int bm = blockIdx.x * BM;
    int bn = blockIdx.y * BN;
    int arows[4];
    #pragma unroll
    for (int q = 0; q < 4; q++) arows[q] = bm + (threadIdx.x >> 2) + 32 * q;
    float acc[4][4][4];
    mma_gemm(g_attn, D_, arows, woW + bn, D_, D_, acc);
    int lane = threadIdx.x & 31, wid = threadIdx.x >> 5;
    int warpM = (wid >> 1) * 64, warpN = (wid & 1) * 32;
    int grp = lane >> 2, qid = lane & 3;
    #pragma unroll
    for (int mf = 0; mf < 4; mf++) {
        int r0 = bm + warpM + mf * 16 + grp;
        #pragma unroll
        for (int nf = 0; nf < 4; nf++) {
            int c0 = bn + warpN + nf * 8 + qid * 2;
            g_x1[(size_t)r0 * D_ + c0]           = acc[mf][nf][0] + bo[c0]     + x[(size_t)r0 * D_ + c0];
            g_x1[(size_t)r0 * D_ + c0 + 1]       = acc[mf][nf][1] + bo[c0 + 1] + x[(size_t)r0 * D_ + c0 + 1];
            g_x1[(size_t)(r0 + 8) * D_ + c0]     = acc[mf][nf][2] + bo[c0]     + x[(size_t)(r0 + 8) * D_ + c0];
            g_x1[(size_t)(r0 + 8) * D_ + c0 + 1] = acc[mf][nf][3] + bo[c0 + 1] + x[(size_t)(r0 + 8) * D_ + c0 + 1];
        }
    }
}

// ---------------- router ----------------
__global__ void __launch_bounds__(128) router_kernel(const float* __restrict__ rw,
                                                     const float* __restrict__ rb) {
    int n = blockIdx.x;
    int tid = threadIdx.x;
    float acc[16];
    #pragma unroll
    for (int e = 0; e < 16; e++) acc[e] = 0.f;
    for (int d = tid; d < D_; d += 128) {
        float hv = g_h2[(size_t)n * D_ + d];
        const float4* r4 = (const float4*)(rw + (size_t)d * E_);
        float4 r0 = r4[0], r1 = r4[1], r2 = r4[2], r3 = r4[3];
        acc[0]  += hv * r0.x; acc[1]  += hv * r0.y; acc[2]  += hv * r0.z; acc[3]  += hv * r0.w;
        acc[4]  += hv * r1.x; acc[5]  += hv * r1.y; acc[6]  += hv * r1.z; acc[7]  += hv * r1.w;
        acc[8]  += hv * r2.x; acc[9]  += hv * r2.y; acc[10] += hv * r2.z; acc[11] += hv * r2.w;
        acc[12] += hv * r3.x; acc[13] += hv * r3.y; acc[14] += hv * r3.z; acc[15] += hv * r3.w;
    }
    #pragma unroll
    for (int e = 0; e < 16; e++) {
        #pragma unroll
        for (int off = 16; off; off >>= 1) acc[e] += __shfl_xor_sync(0xffffffffu, acc[e], off);
    }
    __shared__ float part[4][16];
    __shared__ float slog[16];
    int wid = tid >> 5, lane = tid & 31;
    if (lane == 0) {
        #pragma unroll
        for (int e = 0; e < 16; e++) part[wid][e] = acc[e];
    }
    __syncthreads();
    if (tid < 16) {
        float s = part[0][tid] + part[1][tid] + part[2][tid] + part[3][tid];
        slog[tid] = (s + rb[tid]) / 0.1f;
    }
    __syncthreads();
    if (tid == 0) {
        float l[16];
        float m = -1e30f;
        #pragma unroll
        for (int e = 0; e < 16; e++) { l[e] = slog[e]; m = fmaxf(m, l[e]); }
        float sum = 0.f;
        #pragma unroll
        for (int e = 0; e < 16; e++) sum += expf(l[e] - m);
        float invs = 1.0f / sum;
        #pragma unroll
        for (int e = 0; e < 16; e++) atomicAdd(&g_colsum[e], expf(l[e] - m) * invs);
        int i1 = 0;
        #pragma unroll
        for (int e = 1; e < 16; e++) if (l[e] > l[i1]) i1 = e;
        int i2 = (i1 == 0) ? 1 : 0;
        #pragma unroll
        for (int e = 0; e < 16; e++) if (e != i1 && l[e] > l[i2]) i2 = e;
        float e2 = expf(l[i2] - l[i1]);
        g_gate[n * 2 + 0] = 1.0f / (1.0f + e2);
        g_gate[n * 2 + 1] = e2 / (1.0f + e2);
        int p0 = atomicAdd(&g_cnt[i1], 1); g_list[i1 * S_ + p0] = n * 2 + 0;
        int p1 = atomicAdd(&g_cnt[i2], 1); g_list[i2 * S_ + p1] = n * 2 + 1;
    }
}

__global__ void aux_kernel(float* __restrict__ outp) {
    float v = (threadIdx.x < 16) ? g_colsum[threadIdx.x] : 0.f;
    v = v * v;
    #pragma unroll
    for (int off = 16; off; off >>= 1) v += __shfl_xor_sync(0xffffffffu, v, off);
    if (threadIdx.x == 0) outp[0] = v * (1.0f / (float)E_) * 1e-5f;
}

// ---------------- MoE GEMM 1: hmid = silu(X_gather @ w1[e] + b1[e]) ----------------
__global__ void __launch_bounds__(128) moe1_kernel(const float* __restrict__ w1,
                                                   const float* __restrict__ b1) {
    int e = blockIdx.z;
    int cnt = g_cnt[e];
    int bm = blockIdx.x * BM;
    if (bm >= cnt) return;
    int bn = blockIdx.y * BN;
    int arows[4];
    #pragma unroll
    for (int q = 0; q < 4; q++) {
        int ar = bm + (threadIdx.x >> 2) + 32 * q;
        if (ar >= cnt) ar = cnt - 1;
        arows[q] = g_list[e * S_ + ar] >> 1;
    }
    float acc[4][4][4];
    mma_gemm(g_h2, D_, arows, w1 + (size_t)e * D_ * HDIM_ + bn, HDIM_, D_, acc);
    int lane = threadIdx.x & 31, wid = threadIdx.x >> 5;
    int warpM = (wid >> 1) * 64, warpN = (wid & 1) * 32;
    int grp = lane >> 2, qid = lane & 3;
    #pragma unroll
    for (int mf = 0; mf < 4; mf++) {
        int r0 = bm + warpM + mf * 16 + grp;
        #pragma unroll
        for (int nf = 0; nf < 4; nf++) {
            int c0 = bn + warpN + nf * 8 + qid * 2;
            #pragma unroll
            for (int rr = 0; rr < 2; rr++) {
                int r = r0 + rr * 8;
                if (r < cnt) {
                    float t0 = acc[mf][nf][rr * 2 + 0] + b1[e * HDIM_ + c0];
                    float t1 = acc[mf][nf][rr * 2 + 1] + b1[e * HDIM_ + c0 + 1];
                    g_hmid[(size_t)(e * S_ + r) * HDIM_ + c0]     = t0 / (1.0f + expf(-t0));
                    g_hmid[(size_t)(e * S_ + r) * HDIM_ + c0 + 1] = t1 / (1.0f + expf(-t1));
                }
            }
        }
    }
}

// ---------------- MoE GEMM 2: contrib[pair] = gate * (hmid @ w2[e] + b2[e]) ----------------
__global__ void __launch_bounds__(128) moe2_kernel(const float* __restrict__ w2,
                                                   const float* __restrict__ b2) {
    int e = blockIdx.z;
    int cnt = g_cnt[e];
    int bm = blockIdx.x * BM;
    if (bm >= cnt) return;
    int bn = blockIdx.y * BN;
    int arows[4];
    #pragma unroll
    for (int q = 0; q < 4; q++) {
        int ar = bm + (threadIdx.x >> 2) + 32 * q;
        if (ar >= cnt) ar = cnt - 1;
        arows[q] = e * S_ + ar;
    }
    float acc[4][4][4];
    mma_gemm(g_hmid, HDIM_, arows, w2 + (size_t)e * HDIM_ * D_ + bn, D_, HDIM_, acc);
    int lane = threadIdx.x & 31, wid = threadIdx.x >> 5;
    int warpM = (wid >> 1) * 64, warpN = (wid & 1) * 32;
    int grp = lane >> 2, qid = lane & 3;
    #pragma unroll
    for (int mf = 0; mf < 4; mf++) {
        int r0 = bm + warpM + mf * 16 + grp;
        #pragma unroll
        for (int nf = 0; nf < 4; nf++) {
            int c0 = bn + warpN + nf * 8 + qid * 2;
            #pragma unroll
            for (int rr = 0; rr < 2; rr++) {
                int r = r0 + rr * 8;
                if (r < cnt) {
                    int pair = g_list[e * S_ + r];
                    float g = g_gate[pair];
                    g_contrib[(size_t)pair * D_ + c0]     = g * (acc[mf][nf][rr * 2 + 0] + b2[e * D_ + c0]);
                    g_contrib[(size_t)pair * D_ + c0 + 1] = g * (acc[mf][nf][rr * 2 + 1] + b2[e * D_ + c0 + 1]);
                }
            }
        }
    }
}

// ---------------- final combine ----------------
__global__ void __launch_bounds__(256) combine_kernel(float* __restrict__ out) {
    int n = blockIdx.x;
    int d = threadIdx.x * 4;
    float4 a = *(const float4*)&g_x1[(size_t)n * D_ + d];
    float4 b = *(const float4*)&g_contrib[(size_t)(n * 2 + 0) * D_ + d];
    float4 c = *(const float4*)&g_contrib[(size_t)(n * 2 + 1) * D_ + d];
    float4 r;
    r.x = a.x + b.x + c.x; r.y = a.y + b.y + c.y;
    r.z = a.z + b.z + c.z; r.w = a.w + b.w + c.w;
    *(float4*)&out[(size_t)n * D_ + d] = r;
}

// ---------------- host launcher ----------------
extern "C" void kernel_launch(void* const* d_in, const int* in_sizes, int n_in,
                              void* d_out, int out_size) {
    const float* x    = (const float*)d_in[0];
    const float* n1w  = (const float*)d_in[1];
    const float* wq   = (const float*)d_in[2];
    const float* bq   = (const float*)d_in[3];
    const float* wk   = (const float*)d_in[4];
    const float* bk   = (const float*)d_in[5];
    const float* wv   = (const float*)d_in[6];
    const float* bv   = (const float*)d_in[7];
    const float* woW  = (const float*)d_in[8];
    const float* bo   = (const float*)d_in[9];
    const float* sink = (const float*)d_in[10];
    const float* n2w  = (const float*)d_in[11];
    const float* rw   = (const float*)d_in[12];
    const float* rb   = (const float*)d_in[13];
    const float* w1   = (const float*)d_in[14];
    const float* b1   = (const float*)d_in[15];
    const float* w2   = (const float*)d_in[16];
    const float* b2   = (const float*)d_in[17];
    float* out = (float*)d_out;

    zero_kernel<<<1, 32>>>();
    rmsnorm1_kernel<<<S_, 256>>>(x, n1w);
    qkv_kernel<<<dim3(S_ / BM, 24), 128>>>(wq, bq, wk, bk, wv, bv);
    attn_kernel<<<S_, 256>>>(sink);
    wo_kernel<<<dim3(S_ / BM, D_ / BN), 128>>>(woW, bo, x);
    rmsnorm2_kernel<<<S_, 256>>>(n2w);
    router_kernel<<<S_, 128>>>(rw, rb);
    if (out_size > S_ * D_) {
        aux_kernel<<<1, 32>>>(out + (size_t)S_ * D_);
    }
    moe1_kernel<<<dim3(S_ / BM, HDIM_ / BN, E_), 128>>>(w1, b1);
    moe2_kernel<<<dim3(S_ / BM, D_ / BN, E_), 128>>>(w2, b2);
    combine_kernel<<<S_, 256>>>(out);
}